// round 3
// baseline (speedup 1.0000x reference)
#include <cuda_runtime.h>
#include <math.h>
#include <float.h>

#define BB 4
#define CC 256
#define HHH 128
#define WWW 128
#define HW (HHH*WWW)
#define CHW (CC*HW)
#define TOT (BB*CHW)

// ---------------- scratch (device globals; no allocation allowed) ----------------
__device__ float g_bufA[TOT];
__device__ float g_bufB[TOT];
__device__ float g_rmax[BB*CC*HHH];
__device__ float g_cmax[BB*CC*WWW];
__device__ float g_wt_up[CC*9*CC];
__device__ float g_wt_down[CC*9*CC];
__device__ float g_wt_p[CC*9*CC];
__device__ float g_wt_c2[CC*9*CC];
__device__ float g_wt_c1[CC*CC];

// ---------------- weight transpose: OIHW -> [(ic*R + r)*256 + oc] ----------------
__global__ void transpose_w_kernel(const float* __restrict__ src,
                                   float* __restrict__ dst, int R) {
    int i = blockIdx.x * 256 + threadIdx.x;
    int total = CC * CC * R;
    if (i >= total) return;
    int r  = i % R;
    int ic = (i / R) % CC;
    int oc = i / (R * CC);
    dst[(ic * R + r) * CC + oc] = src[i];
}

// ---------------- 3x3 conv + BN (+optional ReLU) ----------------
// CTA: 256 threads, tile = 128 px (8h x 16w) x 128 oc. Thread = 8 px x 8 oc.
template<bool RELU>
__global__ __launch_bounds__(256, 2) void conv3_kernel(
    const float* __restrict__ in, const float* __restrict__ wt,
    const float* __restrict__ gg, const float* __restrict__ bbp,
    const float* __restrict__ mm, const float* __restrict__ vv,
    float* __restrict__ out)
{
    __shared__ float s_in[8][10][18];     // [ic][row][col]
    __shared__ float s_w[8 * 9 * 128];    // [(ic*9 + r)*128 + oc_local]

    const int wt0 = blockIdx.x * 16;
    const int ht0 = blockIdx.y * 8;
    const int b   = blockIdx.z >> 1;
    const int ocb = (blockIdx.z & 1) * 128;
    const int tid = threadIdx.x;
    const int tx  = tid & 15;     // oc group: oc_local = tx*8..tx*8+7
    const int ty  = tid >> 4;     // px group
    const int h_loc = ty >> 1;          // 0..7
    const int wb    = (ty & 1) * 8;     // 0 or 8

    float acc[8][8];
#pragma unroll
    for (int j = 0; j < 8; ++j)
#pragma unroll
        for (int o = 0; o < 8; ++o) acc[j][o] = 0.f;

    const float* inb = in + (size_t)b * CHW;

    for (int ic0 = 0; ic0 < CC; ic0 += 8) {
        __syncthreads();
        // input tile (with halo, zero padded): 8 ic x 10 rows x 18 cols
        for (int l = tid; l < 8 * 10 * 18; l += 256) {
            int col  = l % 18;
            int rest = l / 18;
            int row  = rest % 10;
            int ic   = rest / 10;
            int gh = ht0 + row - 1;
            int gw = wt0 + col - 1;
            float val = 0.f;
            if ((unsigned)gh < HHH && (unsigned)gw < WWW)
                val = inb[(size_t)(ic0 + ic) * HW + gh * WWW + gw];
            s_in[ic][row][col] = val;
        }
        // weights: coalesced rows of 128 floats from transposed layout
        for (int l = tid; l < 8 * 9 * 128; l += 256) {
            int ocl = l & 127;
            int kr  = l >> 7;   // ic_local*9 + r
            s_w[l] = wt[(size_t)(ic0 * 9 + kr) * CC + ocb + ocl];
        }
        __syncthreads();

#pragma unroll 1
        for (int ic = 0; ic < 8; ++ic) {
#pragma unroll
            for (int ky = 0; ky < 3; ++ky) {
                float xin[10];
#pragma unroll
                for (int j = 0; j < 10; ++j) xin[j] = s_in[ic][h_loc + ky][wb + j];
#pragma unroll
                for (int kx = 0; kx < 3; ++kx) {
                    const float4* wp = (const float4*)&s_w[(ic * 9 + ky * 3 + kx) * 128 + tx * 8];
                    float4 w0 = wp[0];
                    float4 w1 = wp[1];
                    float wr[8] = {w0.x, w0.y, w0.z, w0.w, w1.x, w1.y, w1.z, w1.w};
#pragma unroll
                    for (int j = 0; j < 8; ++j) {
                        float xv = xin[j + kx];
#pragma unroll
                        for (int o = 0; o < 8; ++o)
                            acc[j][o] = fmaf(xv, wr[o], acc[j][o]);
                    }
                }
            }
        }
    }

    // epilogue: BN (+ReLU), write 8px x 8oc
#pragma unroll
    for (int o = 0; o < 8; ++o) {
        int oc = ocb + tx * 8 + o;
        float s  = gg[oc] * rsqrtf(vv[oc] + 1e-5f);
        float sh = bbp[oc] - mm[oc] * s;
        float* op = out + ((size_t)b * CC + oc) * HW + (ht0 + h_loc) * WWW + wt0 + wb;
#pragma unroll
        for (int j = 0; j < 8; ++j) {
            float v = acc[j][o] * s + sh;
            if (RELU) v = fmaxf(v, 0.f);
            op[j] = v;
        }
    }
}

// ---------------- row max over W (one warp per row) ----------------
__global__ void rowmax_kernel(const float* __restrict__ in, float* __restrict__ out) {
    int row  = blockIdx.x * 8 + (threadIdx.x >> 5);
    int lane = threadIdx.x & 31;
    const float* p = in + (size_t)row * WWW;
    float m = fmaxf(fmaxf(p[lane], p[lane + 32]), fmaxf(p[lane + 64], p[lane + 96]));
#pragma unroll
    for (int s = 16; s > 0; s >>= 1)
        m = fmaxf(m, __shfl_xor_sync(0xFFFFFFFFu, m, s));
    if (lane == 0) out[row] = m;
}

// ---------------- column max over H ----------------
__global__ void colmax_kernel(const float* __restrict__ in, float* __restrict__ out) {
    int idx = blockIdx.x * 256 + threadIdx.x;   // (b*C + c)*W + w
    int w  = idx & 127;
    int bc = idx >> 7;
    const float* p = in + (size_t)bc * HW + w;
    float m = -FLT_MAX;
#pragma unroll 4
    for (int h = 0; h < HHH; ++h) m = fmaxf(m, p[h * WWW]);
    out[idx] = m;
}

// ---------------- S = Rmax (bcast over w) + Cmax (bcast over h) ----------------
__global__ void builds_kernel(const float* __restrict__ rmax,
                              const float* __restrict__ cmax,
                              float* __restrict__ out) {
    int i = blockIdx.x * 256 + threadIdx.x;
    int w   = i & 127;
    int bch = i >> 7;          // bc*128 + h
    int bc  = i >> 14;
    out[i] = rmax[bch] + cmax[bc * 128 + w];
}

// ---------------- fused: relu( merge + BN(conv1x1(x)) ) ----------------
__global__ __launch_bounds__(256, 2) void fused1x1_kernel(
    const float* __restrict__ x, const float* __restrict__ wt1,
    const float* __restrict__ gg, const float* __restrict__ bbp,
    const float* __restrict__ mm, const float* __restrict__ vv,
    const float* __restrict__ merge, float* __restrict__ out)
{
    __shared__ float s_x[16 * 128];
    __shared__ float s_w[16 * 128];
    const int ocb = blockIdx.x * 128;
    const int h   = blockIdx.y;
    const int b   = blockIdx.z;
    const int tid = threadIdx.x;
    const int tx = tid & 15;
    const int ty = tid >> 4;

    float acc[8][8];
#pragma unroll
    for (int j = 0; j < 8; ++j)
#pragma unroll
        for (int o = 0; o < 8; ++o) acc[j][o] = 0.f;

    for (int ic0 = 0; ic0 < CC; ic0 += 16) {
        __syncthreads();
        for (int l = tid; l < 2048; l += 256) {
            int col = l & 127;
            int ic  = l >> 7;
            s_x[l] = x[((size_t)(b * CC + ic0 + ic)) * HW + h * WWW + col];
            s_w[l] = wt1[(ic0 + ic) * CC + ocb + col];
        }
        __syncthreads();
#pragma unroll 1
        for (int ic = 0; ic < 16; ++ic) {
            float xr[8];
#pragma unroll
            for (int j = 0; j < 8; ++j) xr[j] = s_x[ic * 128 + ty * 8 + j];
            const float4* wp = (const float4*)&s_w[ic * 128 + tx * 8];
            float4 w0 = wp[0];
            float4 w1 = wp[1];
            float wr[8] = {w0.x, w0.y, w0.z, w0.w, w1.x, w1.y, w1.z, w1.w};
#pragma unroll
            for (int j = 0; j < 8; ++j)
#pragma unroll
                for (int o = 0; o < 8; ++o)
                    acc[j][o] = fmaf(xr[j], wr[o], acc[j][o]);
        }
    }

#pragma unroll
    for (int o = 0; o < 8; ++o) {
        int oc = ocb + tx * 8 + o;
        float s  = gg[oc] * rsqrtf(vv[oc] + 1e-5f);
        float sh = bbp[oc] - mm[oc] * s;
        size_t base = ((size_t)b * CC + oc) * HW + h * WWW + ty * 8;
#pragma unroll
        for (int j = 0; j < 8; ++j) {
            float v = acc[j][o] * s + sh + merge[base + j];
            out[base + j] = fmaxf(v, 0.f);
        }
    }
}

// ---------------- launch ----------------
extern "C" void kernel_launch(void* const* d_in, const int* in_sizes, int n_in,
                              void* d_out, int out_size) {
    (void)in_sizes; (void)n_in; (void)out_size;
    const float* x      = (const float*)d_in[0];
    const float* w_up   = (const float*)d_in[1];
    const float* g_up   = (const float*)d_in[2];
    const float* b_up   = (const float*)d_in[3];
    const float* m_up   = (const float*)d_in[4];
    const float* v_up   = (const float*)d_in[5];
    const float* w_down = (const float*)d_in[6];
    const float* g_down = (const float*)d_in[7];
    const float* b_down = (const float*)d_in[8];
    const float* m_down = (const float*)d_in[9];
    const float* v_down = (const float*)d_in[10];
    const float* w_p    = (const float*)d_in[11];
    const float* g_p    = (const float*)d_in[12];
    const float* b_p    = (const float*)d_in[13];
    const float* m_p    = (const float*)d_in[14];
    const float* v_p    = (const float*)d_in[15];
    const float* w_c1   = (const float*)d_in[16];
    const float* g_c1   = (const float*)d_in[17];
    const float* b_c1   = (const float*)d_in[18];
    const float* m_c1   = (const float*)d_in[19];
    const float* v_c1   = (const float*)d_in[20];
    const float* w_c2   = (const float*)d_in[21];
    const float* g_c2   = (const float*)d_in[22];
    const float* b_c2   = (const float*)d_in[23];
    const float* m_c2   = (const float*)d_in[24];
    const float* v_c2   = (const float*)d_in[25];
    float* out = (float*)d_out;

    float *A, *B, *rmax, *cmax, *wtu, *wtd, *wtp, *wtc2, *wtc1;
    cudaGetSymbolAddress((void**)&A,    g_bufA);
    cudaGetSymbolAddress((void**)&B,    g_bufB);
    cudaGetSymbolAddress((void**)&rmax, g_rmax);
    cudaGetSymbolAddress((void**)&cmax, g_cmax);
    cudaGetSymbolAddress((void**)&wtu,  g_wt_up);
    cudaGetSymbolAddress((void**)&wtd,  g_wt_down);
    cudaGetSymbolAddress((void**)&wtp,  g_wt_p);
    cudaGetSymbolAddress((void**)&wtc2, g_wt_c2);
    cudaGetSymbolAddress((void**)&wtc1, g_wt_c1);

    const int TB = 256;
    int nt9 = CC * CC * 9;
    transpose_w_kernel<<<(nt9 + TB - 1) / TB, TB>>>(w_up,   wtu,  9);
    transpose_w_kernel<<<(nt9 + TB - 1) / TB, TB>>>(w_down, wtd,  9);
    transpose_w_kernel<<<(nt9 + TB - 1) / TB, TB>>>(w_p,    wtp,  9);
    transpose_w_kernel<<<(nt9 + TB - 1) / TB, TB>>>(w_c2,   wtc2, 9);
    transpose_w_kernel<<<(CC * CC + TB - 1) / TB, TB>>>(w_c1, wtc1, 1);

    dim3 cgrid(8, 16, 8);   // w-tiles, h-tiles, b*2 + oc_block

    // up / down conv-bn-relu
    conv3_kernel<true><<<cgrid, TB>>>(x, wtu, g_up, b_up, m_up, v_up, A);
    conv3_kernel<true><<<cgrid, TB>>>(x, wtd, g_down, b_down, m_down, v_down, B);

    // corner pools collapse to global row/col max
    rowmax_kernel<<<(BB * CC * HHH) / 8, TB>>>(A, rmax);
    colmax_kernel<<<(BB * CC * WWW) / TB, TB>>>(B, cmax);
    builds_kernel<<<TOT / TB, TB>>>(rmax, cmax, A);

    // merge = BN(conv3x3(S))
    conv3_kernel<false><<<cgrid, TB>>>(A, wtp, g_p, b_p, m_p, v_p, B);

    // relu1 = relu(merge + BN(conv1x1(x)))
    fused1x1_kernel<<<dim3(2, 128, 4), TB>>>(x, wtc1, g_c1, b_c1, m_c1, v_c1, B, A);

    // out = CBR(relu1, w_c2)
    conv3_kernel<true><<<cgrid, TB>>>(A, wtc2, g_c2, b_c2, m_c2, v_c2, out);
}

// round 7
// speedup vs baseline: 3.0221x; 3.0221x over previous
#include <cuda_runtime.h>
#include <cuda_bf16.h>
#include <math.h>
#include <float.h>
#include <stdint.h>

#define BBATCH 4
#define CCH 256
#define HH 128
#define WWD 128
#define HW (HH*WWD)
#define CHW (CCH*HW)
#define TOTN (BBATCH*CHW)
#define PH 130
#define PSZ (PH*PH)
#define PADTOT (BBATCH*PSZ*CCH)

// ---------------- device scratch (256B-aligned: vector/cp.async access) ----------------
__device__ __align__(256) float g_bufA[TOTN];
__device__ __align__(256) float g_bufB[TOTN];
__device__ __align__(256) __nv_bfloat16 g_pxh[PADTOT];
__device__ __align__(256) __nv_bfloat16 g_pxl[PADTOT];
__device__ __align__(256) __nv_bfloat16 g_pth[PADTOT];
__device__ __align__(256) __nv_bfloat16 g_ptl[PADTOT];
__device__ __align__(256) float g_rmaxT[BBATCH*HH*CCH];   // [b][h][c]
__device__ __align__(256) float g_cmaxT[BBATCH*WWD*CCH];  // [b][w][c]
__device__ __align__(256) __nv_bfloat16 g_blob1[4*4*9*16384];
__device__ __align__(256) __nv_bfloat16 g_blobP[2*4*9*16384];
__device__ __align__(256) __nv_bfloat16 g_blobC2[2*4*9*16384];
__device__ __align__(256) __nv_bfloat16 g_blobC1[2*4*1*16384];

// ---------------- PTX helpers (all legal on plain sm_100) ----------------
__device__ __forceinline__ uint32_t cvta_smem(const void* p) {
    uint32_t a;
    asm("{ .reg .u64 t; cvta.to.shared.u64 t, %1; cvt.u32.u64 %0, t; }" : "=r"(a) : "l"(p));
    return a;
}
__device__ __forceinline__ void cpa16(uint32_t s, const void* g) {
    asm volatile("{ .reg .u64 ga; cvta.to.global.u64 ga, %1; cp.async.cg.shared.global [%0], [ga], 16; }"
        :: "r"(s), "l"(g) : "memory");
}
#define CP_COMMIT() asm volatile("cp.async.commit_group;" ::: "memory")
#define CP_WAIT(n)  asm volatile("cp.async.wait_group %0;" :: "n"(n) : "memory")

__device__ __forceinline__ void ldsm4(uint32_t* r, uint32_t addr) {
    asm volatile("ldmatrix.sync.aligned.m8n8.x4.shared.b16 {%0,%1,%2,%3}, [%4];"
        : "=r"(r[0]), "=r"(r[1]), "=r"(r[2]), "=r"(r[3]) : "r"(addr));
}
__device__ __forceinline__ void mma16816(float* c, const uint32_t* a, const uint32_t* b) {
    asm volatile("mma.sync.aligned.m16n8k16.row.col.f32.bf16.bf16.f32 "
        "{%0,%1,%2,%3}, {%4,%5,%6,%7}, {%8,%9}, {%0,%1,%2,%3};"
        : "+f"(c[0]), "+f"(c[1]), "+f"(c[2]), "+f"(c[3])
        : "r"(a[0]), "r"(a[1]), "r"(a[2]), "r"(a[3]), "r"(b[0]), "r"(b[1]));
}

// ---------------- mma.sync conv: CTA = 128 oc x 128 px (one W row) ----------------
// SMEM per buffer (64KB): A_hi 16K | A_lo 16K | B_hi 16K | B_lo 16K. x2 buffers + 512B rmax.
// A tile: [oc 128][k 64] bf16, rows 128B, 16B-chunk swizzle (kc ^ (row&7)).
// B tile: [px 128][k 64] bf16, same swizzle.
// EPI 0: fused up+down (z0,1 up -> rowmax to out0[b][h][c]; z2,3 down -> relu map out1 NCHW)
// EPI 1: conv_p: relu(v + aux) -> out0
// EPI 2: conv_c2: relu(v) -> out0
// EPI 3: 1x1 (1 shift): v -> out0
#define CONV_SMEM 131584
template<int EPI>
__global__ __launch_bounds__(256, 1) void conv_mma(
    const __nv_bfloat16* __restrict__ in_hi, const __nv_bfloat16* __restrict__ in_lo,
    const __nv_bfloat16* __restrict__ wblob,
    const float* __restrict__ gA, const float* __restrict__ bA,
    const float* __restrict__ mA, const float* __restrict__ vA,
    const float* __restrict__ gB, const float* __restrict__ bB,
    const float* __restrict__ mB, const float* __restrict__ vB,
    const float* __restrict__ aux, float* __restrict__ out0, float* __restrict__ out1)
{
    constexpr int NSH   = (EPI == 3) ? 1 : 9;
    constexpr int NSTEP = 4 * NSH;
    extern __shared__ char smem[];
    const uint32_t sb = cvta_smem(smem);
    float* rsm = (float*)(smem + 131072);

    const int tid  = threadIdx.x;
    const int h    = blockIdx.x;
    const int b    = blockIdx.y;
    const int z    = blockIdx.z;
    const int lane = tid & 31;
    const int wid  = tid >> 5;
    const int warp_m = wid >> 2;   // 0..1 (64 oc each)
    const int warp_n = wid & 3;    // 0..3 (32 px each)
    const int lrow = lane & 15;
    const int lcol = lane >> 4;

    if (EPI == 0 && z < 2 && tid < 128) rsm[tid] = 0.f;

    float c[4][4][4];
#pragma unroll
    for (int i = 0; i < 4; ++i)
#pragma unroll
        for (int j = 0; j < 4; ++j)
#pragma unroll
            for (int r = 0; r < 4; ++r) c[i][j][r] = 0.f;

    const size_t inb = (size_t)b * PSZ * CCH;

    auto stage = [&](int s, int buf) {
        const int chunk = s / NSH;
        const int r     = s % NSH;
        const int dy    = (NSH == 9) ? (r / 3 - 1) : 0;
        const int dx    = (NSH == 9) ? (r % 3 - 1) : 0;
        const uint32_t base = sb + buf * 65536;
        // A: identity copy of prepacked swizzled image (hi 16K + lo 16K)
        const char* asrc = (const char*)wblob + (size_t)((z * 4 + chunk) * NSH + r) * 32768;
#pragma unroll
        for (int t = 0; t < 8; ++t) {
            int i = tid + t * 256;
            cpa16(base + i * 16, asrc + i * 16);
        }
        // B: padded [h][w][c] -> [px][k] swizzled
        const __nv_bfloat16* bh = in_hi + inb + ((size_t)(h + dy + 1) * PH + (dx + 1)) * CCH + chunk * 64;
        const __nv_bfloat16* bl = in_lo + inb + ((size_t)(h + dy + 1) * PH + (dx + 1)) * CCH + chunk * 64;
#pragma unroll
        for (int t = 0; t < 4; ++t) {
            int i  = tid + t * 256;
            int p  = i >> 3;
            int kc = i & 7;
            uint32_t dst = base + 32768 + p * 128 + ((kc ^ (p & 7)) * 16);
            cpa16(dst, bh + p * CCH + kc * 8);
            cpa16(dst + 16384, bl + p * CCH + kc * 8);
        }
        CP_COMMIT();
    };

    stage(0, 0);
    for (int s = 0; s < NSTEP; ++s) {
        const int buf = s & 1;
        if (s + 1 < NSTEP) { stage(s + 1, (s + 1) & 1); CP_WAIT(1); }
        else               { CP_WAIT(0); }
        __syncthreads();

        const uint32_t Ahi = sb + buf * 65536;
        const uint32_t Alo = Ahi + 16384;
        const uint32_t Bhi = Ahi + 32768;
        const uint32_t Blo = Ahi + 49152;

#pragma unroll
        for (int kk = 0; kk < 4; ++kk) {
            const int kc = kk * 2 + lcol;
            uint32_t ah[4][4], al[4][4], bh[4][2], bl2[4][2];
#pragma unroll
            for (int i = 0; i < 4; ++i) {
                int row = warp_m * 64 + i * 16 + lrow;
                uint32_t off = (uint32_t)(row * 128 + ((kc ^ (row & 7)) * 16));
                ldsm4(ah[i], Ahi + off);
            }
#pragma unroll
            for (int j = 0; j < 2; ++j) {
                int row = warp_n * 32 + j * 16 + lrow;
                uint32_t off = (uint32_t)(row * 128 + ((kc ^ (row & 7)) * 16));
                uint32_t q[4];
                ldsm4(q, Bhi + off);
                bh[j * 2 + 0][0] = q[0]; bh[j * 2 + 0][1] = q[2];
                bh[j * 2 + 1][0] = q[1]; bh[j * 2 + 1][1] = q[3];
            }
#pragma unroll
            for (int i = 0; i < 4; ++i)
#pragma unroll
                for (int j = 0; j < 4; ++j) mma16816(c[i][j], ah[i], bh[j]);
#pragma unroll
            for (int i = 0; i < 4; ++i) {
                int row = warp_m * 64 + i * 16 + lrow;
                uint32_t off = (uint32_t)(row * 128 + ((kc ^ (row & 7)) * 16));
                ldsm4(al[i], Alo + off);
            }
#pragma unroll
            for (int i = 0; i < 4; ++i)
#pragma unroll
                for (int j = 0; j < 4; ++j) mma16816(c[i][j], al[i], bh[j]);
#pragma unroll
            for (int j = 0; j < 2; ++j) {
                int row = warp_n * 32 + j * 16 + lrow;
                uint32_t off = (uint32_t)(row * 128 + ((kc ^ (row & 7)) * 16));
                uint32_t q[4];
                ldsm4(q, Blo + off);
                bl2[j * 2 + 0][0] = q[0]; bl2[j * 2 + 0][1] = q[2];
                bl2[j * 2 + 1][0] = q[1]; bl2[j * 2 + 1][1] = q[3];
            }
#pragma unroll
            for (int i = 0; i < 4; ++i)
#pragma unroll
                for (int j = 0; j < 4; ++j) mma16816(c[i][j], ah[i], bl2[j]);
        }
        __syncthreads();
    }

    // ---- epilogue ----
    const int quad = lane >> 2;
    const int tq   = lane & 3;
    const int ocb  = (EPI == 0) ? (z & 1) * 128 : z * 128;
    const bool up  = (EPI == 0) && (z < 2);
    const float* gp = (EPI == 0 && z >= 2) ? gB : gA;
    const float* bp = (EPI == 0 && z >= 2) ? bB : bA;
    const float* mp = (EPI == 0 && z >= 2) ? mB : mA;
    const float* vp = (EPI == 0 && z >= 2) ? vB : vA;

#pragma unroll
    for (int i = 0; i < 4; ++i) {
#pragma unroll
        for (int h2 = 0; h2 < 2; ++h2) {
            const int ocl = warp_m * 64 + i * 16 + quad + h2 * 8;
            const int oc  = ocb + ocl;
            const float sc = gp[oc] * rsqrtf(vp[oc] + 1e-5f);
            const float sh = bp[oc] - mp[oc] * sc;
            if (up) {
                float m = 0.f;
#pragma unroll
                for (int j = 0; j < 4; ++j) {
                    m = fmaxf(m, c[i][j][h2 * 2 + 0] * sc + sh);
                    m = fmaxf(m, c[i][j][h2 * 2 + 1] * sc + sh);
                }
                atomicMax((unsigned*)&rsm[ocl], __float_as_uint(fmaxf(m, 0.f)));
            } else {
                size_t rowbase = ((size_t)b * CCH + oc) * HW + (size_t)h * WWD;
#pragma unroll
                for (int j = 0; j < 4; ++j) {
                    const int w = warp_n * 32 + j * 8 + tq * 2;
                    float v0 = c[i][j][h2 * 2 + 0] * sc + sh;
                    float v1 = c[i][j][h2 * 2 + 1] * sc + sh;
                    if (EPI == 1) {
                        float2 a2 = *(const float2*)(aux + rowbase + w);
                        v0 = fmaxf(v0 + a2.x, 0.f);
                        v1 = fmaxf(v1 + a2.y, 0.f);
                        *(float2*)(out0 + rowbase + w) = make_float2(v0, v1);
                    } else if (EPI == 3) {
                        *(float2*)(out0 + rowbase + w) = make_float2(v0, v1);
                    } else {
                        float* dst = (EPI == 0) ? out1 : out0;
                        *(float2*)(dst + rowbase + w) = make_float2(fmaxf(v0, 0.f), fmaxf(v1, 0.f));
                    }
                }
            }
        }
    }
    if (up) {
        __syncthreads();
        if (tid < 128)
            out0[((size_t)b * HH + h) * CCH + z * 128 + tid] = rsm[tid];
    }
}

// ---------------- weight prepack: OIHW fp32 -> swizzled bf16 hi/lo SMEM images ----------------
// ONE THREAD PER (image, ocl, icl) -> writes hi AND lo. total = images * 8192.
__global__ void prepack_kernel(const float* __restrict__ srcA, const float* __restrict__ srcB,
                               int zsplit, int NSH, __nv_bfloat16* __restrict__ blob, int total)
{
    int idx = blockIdx.x * 256 + threadIdx.x;
    if (idx >= total) return;
    int icl  = idx & 63;
    int ocl  = (idx >> 6) & 127;
    int rest = idx >> 13;
    int r = rest % NSH; rest /= NSH;
    int chunk = rest & 3;
    int zz    = rest >> 2;
    const float* src = srcA;
    int o = zz * 128 + ocl;
    if (zz >= zsplit) { src = srcB; o = (zz - zsplit) * 128 + ocl; }
    int ic = chunk * 64 + icl;
    float w = src[(size_t)(o * 256 + ic) * NSH + r];
    __nv_bfloat16 hi = __float2bfloat16_rn(w);
    __nv_bfloat16 lo = __float2bfloat16_rn(w - __bfloat162float(hi));
    size_t base = (size_t)((zz * 4 + chunk) * NSH + r) * 16384;
    uint32_t off = (uint32_t)(ocl * 64 + (((icl >> 3) ^ (ocl & 7)) * 8) + (icl & 7));
    blob[base + off]        = hi;
    blob[base + 8192 + off] = lo;
}

// ---------------- zero borders of the 4 padded buffers ----------------
__global__ void zero_border_kernel(__nv_bfloat16* a, __nv_bfloat16* b,
                                   __nv_bfloat16* c, __nv_bfloat16* d) {
    int idx = blockIdx.x * 256 + threadIdx.x;   // 4*516*256
    int ch   = idx & 255;
    int rest = idx >> 8;
    int p    = rest % 516;
    int bb   = rest / 516;
    int h, w;
    if (p < 260) { h = (p < 130) ? 0 : 129; w = p % 130; }
    else         { int q = p - 260; h = 1 + (q & 127); w = (q >> 7) * 129; }
    size_t i = ((size_t)bb * PSZ + (size_t)h * PH + w) * CCH + ch;
    a[i] = __float2bfloat16(0.f); b[i] = __float2bfloat16(0.f);
    c[i] = __float2bfloat16(0.f); d[i] = __float2bfloat16(0.f);
}

// ---------------- fp32 NCHW -> padded [h][w][c] bf16 hi/lo ----------------
__global__ void pad_convert_kernel(const float* __restrict__ src,
                                   __nv_bfloat16* __restrict__ phb,
                                   __nv_bfloat16* __restrict__ plb)
{
    __shared__ float s[256][33];
    const int w0 = blockIdx.x * 32;
    const int h  = blockIdx.y;
    const int b  = blockIdx.z;
    const int tid = threadIdx.x;
    const int wl8 = tid & 31;
#pragma unroll 4
    for (int i = 0; i < 32; ++i) {
        int c = i * 8 + (tid >> 5);
        s[c][wl8] = src[((size_t)(b * CCH + c) * HH + h) * WWD + w0 + wl8];
    }
    __syncthreads();
    const int wl = tid >> 3;
    const int cg = (tid & 7) * 32;
    __align__(16) __nv_bfloat16 hi[32];
    __align__(16) __nv_bfloat16 lo[32];
#pragma unroll
    for (int j = 0; j < 32; ++j) {
        float v = s[cg + j][wl];
        hi[j] = __float2bfloat16_rn(v);
        lo[j] = __float2bfloat16_rn(v - __bfloat162float(hi[j]));
    }
    size_t base = ((size_t)b * PSZ + (size_t)(h + 1) * PH + (w0 + wl + 1)) * CCH + cg;
    uint4* hp = (uint4*)(phb + base);
    uint4* lp = (uint4*)(plb + base);
    const uint4* hs = (const uint4*)hi;
    const uint4* ls = (const uint4*)lo;
#pragma unroll
    for (int q = 0; q < 4; ++q) { hp[q] = hs[q]; lp[q] = ls[q]; }
}

// ---------------- column max over H (NCHW in) -> [b][w][c] ----------------
__global__ void colmaxT_kernel(const float* __restrict__ in, float* __restrict__ outT) {
    int idx = blockIdx.x * 256 + threadIdx.x;   // (b*256+oc)*128 + w
    int w  = idx & 127;
    int bc = idx >> 7;
    int oc = bc & 255;
    int b  = bc >> 8;
    const float* p = in + (size_t)bc * HW + w;
    float m = -FLT_MAX;
#pragma unroll 4
    for (int h = 0; h < HH; ++h) m = fmaxf(m, p[(size_t)h * WWD]);
    outT[((size_t)b * WWD + w) * CCH + oc] = m;
}

// ---------------- S = rmax + cmax -> padded bf16 hi/lo ----------------
__global__ void sbuild_kernel(const float* __restrict__ rT, const float* __restrict__ cT,
                              __nv_bfloat16* __restrict__ phb, __nv_bfloat16* __restrict__ plb)
{
    const int w = blockIdx.x, h = blockIdx.y, b = blockIdx.z;
    const int c = threadIdx.x;
    float v = rT[((size_t)b * HH + h) * CCH + c] + cT[((size_t)b * WWD + w) * CCH + c];
    __nv_bfloat16 hi = __float2bfloat16_rn(v);
    __nv_bfloat16 lo = __float2bfloat16_rn(v - __bfloat162float(hi));
    size_t idx = ((size_t)b * PSZ + (size_t)(h + 1) * PH + (w + 1)) * CCH + c;
    phb[idx] = hi;
    plb[idx] = lo;
}

// ---------------- launch ----------------
extern "C" void kernel_launch(void* const* d_in, const int* in_sizes, int n_in,
                              void* d_out, int out_size) {
    (void)in_sizes; (void)n_in; (void)out_size;
    const float* x      = (const float*)d_in[0];
    const float* w_up   = (const float*)d_in[1];
    const float* g_up   = (const float*)d_in[2];
    const float* b_up   = (const float*)d_in[3];
    const float* m_up   = (const float*)d_in[4];
    const float* v_up   = (const float*)d_in[5];
    const float* w_down = (const float*)d_in[6];
    const float* g_down = (const float*)d_in[7];
    const float* b_down = (const float*)d_in[8];
    const float* m_down = (const float*)d_in[9];
    const float* v_down = (const float*)d_in[10];
    const float* w_p    = (const float*)d_in[11];
    const float* g_p    = (const float*)d_in[12];
    const float* b_p    = (const float*)d_in[13];
    const float* m_p    = (const float*)d_in[14];
    const float* v_p    = (const float*)d_in[15];
    const float* w_c1   = (const float*)d_in[16];
    const float* g_c1   = (const float*)d_in[17];
    const float* b_c1   = (const float*)d_in[18];
    const float* m_c1   = (const float*)d_in[19];
    const float* v_c1   = (const float*)d_in[20];
    const float* w_c2   = (const float*)d_in[21];
    const float* g_c2   = (const float*)d_in[22];
    const float* b_c2   = (const float*)d_in[23];
    const float* m_c2   = (const float*)d_in[24];
    const float* v_c2   = (const float*)d_in[25];
    float* out = (float*)d_out;

    float *bufA, *bufB, *rmaxT, *cmaxT;
    __nv_bfloat16 *pxh, *pxl, *pth, *ptl, *bl1, *blP, *blC2, *blC1;
    cudaGetSymbolAddress((void**)&bufA,  g_bufA);
    cudaGetSymbolAddress((void**)&bufB,  g_bufB);
    cudaGetSymbolAddress((void**)&rmaxT, g_rmaxT);
    cudaGetSymbolAddress((void**)&cmaxT, g_cmaxT);
    cudaGetSymbolAddress((void**)&pxh,   g_pxh);
    cudaGetSymbolAddress((void**)&pxl,   g_pxl);
    cudaGetSymbolAddress((void**)&pth,   g_pth);
    cudaGetSymbolAddress((void**)&ptl,   g_ptl);
    cudaGetSymbolAddress((void**)&bl1,   g_blob1);
    cudaGetSymbolAddress((void**)&blP,   g_blobP);
    cudaGetSymbolAddress((void**)&blC2,  g_blobC2);
    cudaGetSymbolAddress((void**)&blC1,  g_blobC1);

    cudaFuncSetAttribute(conv_mma<0>, cudaFuncAttributeMaxDynamicSharedMemorySize, CONV_SMEM);
    cudaFuncSetAttribute(conv_mma<1>, cudaFuncAttributeMaxDynamicSharedMemorySize, CONV_SMEM);
    cudaFuncSetAttribute(conv_mma<2>, cudaFuncAttributeMaxDynamicSharedMemorySize, CONV_SMEM);
    cudaFuncSetAttribute(conv_mma<3>, cudaFuncAttributeMaxDynamicSharedMemorySize, CONV_SMEM);

    // totals = images * 8192 (each thread writes its hi+lo pair)
    prepack_kernel<<<1179648/256, 256>>>(w_up, w_down, 2, 9, bl1, 1179648);  // 144 imgs
    prepack_kernel<<<589824/256,  256>>>(w_p,  w_p,    2, 9, blP, 589824);   // 72 imgs
    prepack_kernel<<<589824/256,  256>>>(w_c2, w_c2,   2, 9, blC2, 589824);  // 72 imgs
    prepack_kernel<<<65536/256,   256>>>(w_c1, w_c1,   2, 1, blC1, 65536);   // 8 imgs
    zero_border_kernel<<<(4*516*256)/256, 256>>>(pxh, pxl, pth, ptl);
    pad_convert_kernel<<<dim3(4,128,4), 256>>>(x, pxh, pxl);

    // fused up+down: z0,1 -> rowmaxT; z2,3 -> down relu map in bufA
    conv_mma<0><<<dim3(HH,BBATCH,4), 256, CONV_SMEM>>>(pxh, pxl, bl1,
        g_up, b_up, m_up, v_up, g_down, b_down, m_down, v_down,
        nullptr, rmaxT, bufA);
    colmaxT_kernel<<<512, 256>>>(bufA, cmaxT);
    sbuild_kernel<<<dim3(128,128,4), 256>>>(rmaxT, cmaxT, pth, ptl);

    // bn1 = BN(conv1x1(x)) -> bufB
    conv_mma<3><<<dim3(HH,BBATCH,2), 256, CONV_SMEM>>>(pxh, pxl, blC1,
        g_c1, b_c1, m_c1, v_c1, g_c1, b_c1, m_c1, v_c1,
        nullptr, bufB, nullptr);

    // relu1 = relu(BN(conv_p(S)) + bn1) -> bufA
    conv_mma<1><<<dim3(HH,BBATCH,2), 256, CONV_SMEM>>>(pth, ptl, blP,
        g_p, b_p, m_p, v_p, g_p, b_p, m_p, v_p,
        bufB, bufA, nullptr);

    pad_convert_kernel<<<dim3(4,128,4), 256>>>(bufA, pth, ptl);

    // out = CBR(relu1, w_c2)
    conv_mma<2><<<dim3(HH,BBATCH,2), 256, CONV_SMEM>>>(pth, ptl, blC2,
        g_c2, b_c2, m_c2, v_c2, g_c2, b_c2, m_c2, v_c2,
        nullptr, out, nullptr);
}

// round 8
// speedup vs baseline: 3.0646x; 1.0141x over previous
#include <cuda_runtime.h>
#include <cuda_bf16.h>
#include <math.h>
#include <float.h>
#include <stdint.h>

#define BBATCH 4
#define CCH 256
#define HH 128
#define WWD 128
#define HW (HH*WWD)
#define CHW (CCH*HW)
#define TOTN (BBATCH*CHW)
#define PH 130
#define PSZ (PH*PH)
#define PADTOT (BBATCH*PSZ*CCH)

// ---------------- device scratch ----------------
__device__ __align__(256) float g_bufA[TOTN];
__device__ __align__(256) float g_bufB[TOTN];
__device__ __align__(256) __nv_bfloat16 g_pxh[PADTOT];
__device__ __align__(256) __nv_bfloat16 g_pxl[PADTOT];
__device__ __align__(256) __nv_bfloat16 g_pth[PADTOT];
__device__ __align__(256) __nv_bfloat16 g_ptl[PADTOT];
__device__ __align__(256) float g_rmaxT[BBATCH*HH*CCH];   // [b][h][c]
__device__ __align__(256) float g_cmaxT[BBATCH*WWD*CCH];  // [b][w][c]
__device__ __align__(256) __nv_bfloat16 g_blob1[4*4*9*16384];
__device__ __align__(256) __nv_bfloat16 g_blobP[2*4*9*16384];
__device__ __align__(256) __nv_bfloat16 g_blobC2[2*4*9*16384];
__device__ __align__(256) __nv_bfloat16 g_blobC1[2*4*1*16384];

// ---------------- PTX helpers (plain sm_100 legal) ----------------
__device__ __forceinline__ uint32_t cvta_smem(const void* p) {
    uint32_t a;
    asm("{ .reg .u64 t; cvta.to.shared.u64 t, %1; cvt.u32.u64 %0, t; }" : "=r"(a) : "l"(p));
    return a;
}
__device__ __forceinline__ void cpa16(uint32_t s, const void* g) {
    asm volatile("{ .reg .u64 ga; cvta.to.global.u64 ga, %1; cp.async.cg.shared.global [%0], [ga], 16; }"
        :: "r"(s), "l"(g) : "memory");
}
#define CP_COMMIT() asm volatile("cp.async.commit_group;" ::: "memory")
#define CP_WAIT(n)  asm volatile("cp.async.wait_group %0;" :: "n"(n) : "memory")

__device__ __forceinline__ void ldsm4(uint32_t* r, uint32_t addr) {
    asm volatile("ldmatrix.sync.aligned.m8n8.x4.shared.b16 {%0,%1,%2,%3}, [%4];"
        : "=r"(r[0]), "=r"(r[1]), "=r"(r[2]), "=r"(r[3]) : "r"(addr));
}
__device__ __forceinline__ void mma16816(float* c, const uint32_t* a, const uint32_t* b) {
    asm volatile("mma.sync.aligned.m16n8k16.row.col.f32.bf16.bf16.f32 "
        "{%0,%1,%2,%3}, {%4,%5,%6,%7}, {%8,%9}, {%0,%1,%2,%3};"
        : "+f"(c[0]), "+f"(c[1]), "+f"(c[2]), "+f"(c[3])
        : "r"(a[0]), "r"(a[1]), "r"(a[2]), "r"(a[3]), "r"(b[0]), "r"(b[1]));
}

// ---------------- mma.sync conv, dx-reuse staging ----------------
// SMEM: Wbuf0 @0 (32K: hi16K+lo16K) | Wbuf1 @32768 | Bbuf0 @65536 (33280: hi 130*128 + lo) |
//       Bbuf1 @98816 | rsm @132096. B staged once per (chunk,dy) = 130 padded px rows;
//       dx handled by ldmatrix row offset (+dx+1).
#define CONV_SMEM 132608
template<int EPI>
__global__ __launch_bounds__(256, 1) void conv_mma(
    const __nv_bfloat16* __restrict__ in_hi, const __nv_bfloat16* __restrict__ in_lo,
    const __nv_bfloat16* __restrict__ wblob,
    const float* __restrict__ gA, const float* __restrict__ bA,
    const float* __restrict__ mA, const float* __restrict__ vA,
    const float* __restrict__ gB, const float* __restrict__ bB,
    const float* __restrict__ mB, const float* __restrict__ vB,
    const float* __restrict__ aux, float* __restrict__ out0, float* __restrict__ out1)
{
    constexpr int NSH   = (EPI == 3) ? 1 : 9;
    constexpr int NSTEP = 4 * NSH;
    constexpr int BSP   = (EPI == 3) ? 1 : 3;   // steps per B stage
    extern __shared__ char smem[];
    const uint32_t sb = cvta_smem(smem);
    float* rsm = (float*)(smem + 132096);

    const int tid  = threadIdx.x;
    const int h    = blockIdx.x;
    const int b    = blockIdx.y;
    const int z    = blockIdx.z;
    const int lane = tid & 31;
    const int wid  = tid >> 5;
    const int warp_m = wid >> 2;   // 0..1 (64 oc each)
    const int warp_n = wid & 3;    // 0..3 (32 px each)
    const int lrow = lane & 15;
    const int lcol = lane >> 4;

    if (EPI == 0 && z < 2 && tid < 128) rsm[tid] = 0.f;

    float c[4][4][4];
#pragma unroll
    for (int i = 0; i < 4; ++i)
#pragma unroll
        for (int j = 0; j < 4; ++j)
#pragma unroll
            for (int r = 0; r < 4; ++r) c[i][j][r] = 0.f;

    const size_t inb = (size_t)b * PSZ * CCH;

    // weights: identity copy of prepacked swizzled image (hi 16K + lo 16K)
    auto stage_w = [&](int s) {
        const uint32_t base = sb + (uint32_t)(s & 1) * 32768;
        const char* asrc = (const char*)wblob + (size_t)((z * 4 + s / NSH) * NSH + (s % NSH)) * 32768;
#pragma unroll
        for (int t = 0; t < 8; ++t) {
            int i = tid + t * 256;
            cpa16(base + i * 16, asrc + i * 16);
        }
    };
    // B: 130 padded px rows of one (chunk, dy) combo, swizzled [px][k]
    auto stage_b = [&](int sid) {
        const int chunk = (EPI == 3) ? sid : sid / 3;
        const int dy    = (EPI == 3) ? 0   : sid % 3 - 1;
        const uint32_t base = sb + 65536 + (uint32_t)(sid & 1) * 33280;
        const __nv_bfloat16* bh = in_hi + inb + (size_t)(h + dy + 1) * PH * CCH + chunk * 64;
        const __nv_bfloat16* bl = in_lo + inb + (size_t)(h + dy + 1) * PH * CCH + chunk * 64;
        for (int i = tid; i < 1040; i += 256) {       // 130 rows x 8 kc
            int wp = i >> 3;
            int kc = i & 7;
            uint32_t dst = base + wp * 128 + ((kc ^ (wp & 7)) * 16);
            cpa16(dst,         bh + (size_t)wp * CCH + kc * 8);
            cpa16(dst + 16640, bl + (size_t)wp * CCH + kc * 8);
        }
    };

    stage_w(0);
    stage_b(0);
    CP_COMMIT();

    for (int s = 0; s < NSTEP; ++s) {
        if (s + 1 < NSTEP) {
            stage_w(s + 1);
            if ((s + 1) % BSP == 0) stage_b((s + 1) / BSP);
            CP_COMMIT();
            CP_WAIT(1);
        } else {
            CP_WAIT(0);
        }
        __syncthreads();

        const uint32_t Ahi = sb + (uint32_t)(s & 1) * 32768;
        const uint32_t Alo = Ahi + 16384;
        const uint32_t Bb  = sb + 65536 + (uint32_t)((s / BSP) & 1) * 33280;
        const uint32_t Bhi = Bb;
        const uint32_t Blo = Bb + 16640;
        const int dxp = (EPI == 3) ? 1 : (s % 3);   // dx+1 in {0,1,2}

#pragma unroll
        for (int kk = 0; kk < 4; ++kk) {
            const int kc = kk * 2 + lcol;
            uint32_t ah[4][4], al[4][4], bh[4][2], bl2[4][2];
#pragma unroll
            for (int i = 0; i < 4; ++i) {
                int row = warp_m * 64 + i * 16 + lrow;
                uint32_t off = (uint32_t)(row * 128 + ((kc ^ (row & 7)) * 16));
                ldsm4(ah[i], Ahi + off);
            }
#pragma unroll
            for (int j = 0; j < 2; ++j) {
                int row = warp_n * 32 + j * 16 + lrow + dxp;
                uint32_t off = (uint32_t)(row * 128 + ((kc ^ (row & 7)) * 16));
                uint32_t q[4];
                ldsm4(q, Bhi + off);
                bh[j * 2 + 0][0] = q[0]; bh[j * 2 + 0][1] = q[2];
                bh[j * 2 + 1][0] = q[1]; bh[j * 2 + 1][1] = q[3];
            }
#pragma unroll
            for (int i = 0; i < 4; ++i)
#pragma unroll
                for (int j = 0; j < 4; ++j) mma16816(c[i][j], ah[i], bh[j]);
#pragma unroll
            for (int i = 0; i < 4; ++i) {
                int row = warp_m * 64 + i * 16 + lrow;
                uint32_t off = (uint32_t)(row * 128 + ((kc ^ (row & 7)) * 16));
                ldsm4(al[i], Alo + off);
            }
#pragma unroll
            for (int i = 0; i < 4; ++i)
#pragma unroll
                for (int j = 0; j < 4; ++j) mma16816(c[i][j], al[i], bh[j]);
#pragma unroll
            for (int j = 0; j < 2; ++j) {
                int row = warp_n * 32 + j * 16 + lrow + dxp;
                uint32_t off = (uint32_t)(row * 128 + ((kc ^ (row & 7)) * 16));
                uint32_t q[4];
                ldsm4(q, Blo + off);
                bl2[j * 2 + 0][0] = q[0]; bl2[j * 2 + 0][1] = q[2];
                bl2[j * 2 + 1][0] = q[1]; bl2[j * 2 + 1][1] = q[3];
            }
#pragma unroll
            for (int i = 0; i < 4; ++i)
#pragma unroll
                for (int j = 0; j < 4; ++j) mma16816(c[i][j], ah[i], bl2[j]);
        }
        __syncthreads();
    }

    // ---- epilogue ----
    const int quad = lane >> 2;
    const int tq   = lane & 3;
    const int ocb  = (EPI == 0) ? (z & 1) * 128 : z * 128;
    const bool up  = (EPI == 0) && (z < 2);
    const float* gp = (EPI == 0 && z >= 2) ? gB : gA;
    const float* bp = (EPI == 0 && z >= 2) ? bB : bA;
    const float* mp = (EPI == 0 && z >= 2) ? mB : mA;
    const float* vp = (EPI == 0 && z >= 2) ? vB : vA;

#pragma unroll
    for (int i = 0; i < 4; ++i) {
#pragma unroll
        for (int h2 = 0; h2 < 2; ++h2) {
            const int ocl = warp_m * 64 + i * 16 + quad + h2 * 8;
            const int oc  = ocb + ocl;
            const float sc = gp[oc] * rsqrtf(vp[oc] + 1e-5f);
            const float sh = bp[oc] - mp[oc] * sc;
            if (up) {
                float m = 0.f;
#pragma unroll
                for (int j = 0; j < 4; ++j) {
                    m = fmaxf(m, c[i][j][h2 * 2 + 0] * sc + sh);
                    m = fmaxf(m, c[i][j][h2 * 2 + 1] * sc + sh);
                }
                atomicMax((unsigned*)&rsm[ocl], __float_as_uint(fmaxf(m, 0.f)));
            } else {
                size_t rowbase = ((size_t)b * CCH + oc) * HW + (size_t)h * WWD;
#pragma unroll
                for (int j = 0; j < 4; ++j) {
                    const int w = warp_n * 32 + j * 8 + tq * 2;
                    float v0 = c[i][j][h2 * 2 + 0] * sc + sh;
                    float v1 = c[i][j][h2 * 2 + 1] * sc + sh;
                    if (EPI == 1) {
                        float2 a2 = *(const float2*)(aux + rowbase + w);
                        v0 = fmaxf(v0 + a2.x, 0.f);
                        v1 = fmaxf(v1 + a2.y, 0.f);
                        *(float2*)(out0 + rowbase + w) = make_float2(v0, v1);
                    } else if (EPI == 3) {
                        *(float2*)(out0 + rowbase + w) = make_float2(v0, v1);
                    } else {
                        float* dst = (EPI == 0) ? out1 : out0;
                        *(float2*)(dst + rowbase + w) = make_float2(fmaxf(v0, 0.f), fmaxf(v1, 0.f));
                    }
                }
            }
        }
    }
    if (up) {
        __syncthreads();
        if (tid < 128)
            out0[((size_t)b * HH + h) * CCH + z * 128 + tid] = rsm[tid];
    }
}

// ---------------- weight prepack: one thread per (image, ocl, icl); total = images*8192 ----------------
__global__ void prepack_kernel(const float* __restrict__ srcA, const float* __restrict__ srcB,
                               int zsplit, int NSH, __nv_bfloat16* __restrict__ blob, int total)
{
    int idx = blockIdx.x * 256 + threadIdx.x;
    if (idx >= total) return;
    int icl  = idx & 63;
    int ocl  = (idx >> 6) & 127;
    int rest = idx >> 13;
    int r = rest % NSH; rest /= NSH;
    int chunk = rest & 3;
    int zz    = rest >> 2;
    const float* src = srcA;
    int o = zz * 128 + ocl;
    if (zz >= zsplit) { src = srcB; o = (zz - zsplit) * 128 + ocl; }
    int ic = chunk * 64 + icl;
    float w = src[(size_t)(o * 256 + ic) * NSH + r];
    __nv_bfloat16 hi = __float2bfloat16_rn(w);
    __nv_bfloat16 lo = __float2bfloat16_rn(w - __bfloat162float(hi));
    size_t base = (size_t)((zz * 4 + chunk) * NSH + r) * 16384;
    uint32_t off = (uint32_t)(ocl * 64 + (((icl >> 3) ^ (ocl & 7)) * 8) + (icl & 7));
    blob[base + off]        = hi;
    blob[base + 8192 + off] = lo;
}

// ---------------- zero borders of the 4 padded buffers ----------------
__global__ void zero_border_kernel(__nv_bfloat16* a, __nv_bfloat16* b,
                                   __nv_bfloat16* c, __nv_bfloat16* d) {
    int idx = blockIdx.x * 256 + threadIdx.x;   // 4*516*256
    int ch   = idx & 255;
    int rest = idx >> 8;
    int p    = rest % 516;
    int bb   = rest / 516;
    int h, w;
    if (p < 260) { h = (p < 130) ? 0 : 129; w = p % 130; }
    else         { int q = p - 260; h = 1 + (q & 127); w = (q >> 7) * 129; }
    size_t i = ((size_t)bb * PSZ + (size_t)h * PH + w) * CCH + ch;
    a[i] = __float2bfloat16(0.f); b[i] = __float2bfloat16(0.f);
    c[i] = __float2bfloat16(0.f); d[i] = __float2bfloat16(0.f);
}

// ---------------- fp32 NCHW -> padded [h][w][c] bf16 hi/lo ----------------
__global__ void pad_convert_kernel(const float* __restrict__ src,
                                   __nv_bfloat16* __restrict__ phb,
                                   __nv_bfloat16* __restrict__ plb)
{
    __shared__ float s[256][33];
    const int w0 = blockIdx.x * 32;
    const int h  = blockIdx.y;
    const int b  = blockIdx.z;
    const int tid = threadIdx.x;
    const int wl8 = tid & 31;
#pragma unroll 4
    for (int i = 0; i < 32; ++i) {
        int c = i * 8 + (tid >> 5);
        s[c][wl8] = src[((size_t)(b * CCH + c) * HH + h) * WWD + w0 + wl8];
    }
    __syncthreads();
    const int wl = tid >> 3;
    const int cg = (tid & 7) * 32;
    __align__(16) __nv_bfloat16 hi[32];
    __align__(16) __nv_bfloat16 lo[32];
#pragma unroll
    for (int j = 0; j < 32; ++j) {
        float v = s[cg + j][wl];
        hi[j] = __float2bfloat16_rn(v);
        lo[j] = __float2bfloat16_rn(v - __bfloat162float(hi[j]));
    }
    size_t base = ((size_t)b * PSZ + (size_t)(h + 1) * PH + (w0 + wl + 1)) * CCH + cg;
    uint4* hp = (uint4*)(phb + base);
    uint4* lp = (uint4*)(plb + base);
    const uint4* hs = (const uint4*)hi;
    const uint4* ls = (const uint4*)lo;
#pragma unroll
    for (int q = 0; q < 4; ++q) { hp[q] = hs[q]; lp[q] = ls[q]; }
}

// ---------------- column max over H (NCHW in) -> [b][w][c] ----------------
__global__ void colmaxT_kernel(const float* __restrict__ in, float* __restrict__ outT) {
    int idx = blockIdx.x * 256 + threadIdx.x;   // (b*256+oc)*128 + w
    int w  = idx & 127;
    int bc = idx >> 7;
    int oc = bc & 255;
    int b  = bc >> 8;
    const float* p = in + (size_t)bc * HW + w;
    float m = -FLT_MAX;
#pragma unroll 4
    for (int h = 0; h < HH; ++h) m = fmaxf(m, p[(size_t)h * WWD]);
    outT[((size_t)b * WWD + w) * CCH + oc] = m;
}

// ---------------- S = rmax + cmax -> padded bf16 hi/lo ----------------
__global__ void sbuild_kernel(const float* __restrict__ rT, const float* __restrict__ cT,
                              __nv_bfloat16* __restrict__ phb, __nv_bfloat16* __restrict__ plb)
{
    const int w = blockIdx.x, h = blockIdx.y, b = blockIdx.z;
    const int c = threadIdx.x;
    float v = rT[((size_t)b * HH + h) * CCH + c] + cT[((size_t)b * WWD + w) * CCH + c];
    __nv_bfloat16 hi = __float2bfloat16_rn(v);
    __nv_bfloat16 lo = __float2bfloat16_rn(v - __bfloat162float(hi));
    size_t idx = ((size_t)b * PSZ + (size_t)(h + 1) * PH + (w + 1)) * CCH + c;
    phb[idx] = hi;
    plb[idx] = lo;
}

// ---------------- launch ----------------
extern "C" void kernel_launch(void* const* d_in, const int* in_sizes, int n_in,
                              void* d_out, int out_size) {
    (void)in_sizes; (void)n_in; (void)out_size;
    const float* x      = (const float*)d_in[0];
    const float* w_up   = (const float*)d_in[1];
    const float* g_up   = (const float*)d_in[2];
    const float* b_up   = (const float*)d_in[3];
    const float* m_up   = (const float*)d_in[4];
    const float* v_up   = (const float*)d_in[5];
    const float* w_down = (const float*)d_in[6];
    const float* g_down = (const float*)d_in[7];
    const float* b_down = (const float*)d_in[8];
    const float* m_down = (const float*)d_in[9];
    const float* v_down = (const float*)d_in[10];
    const float* w_p    = (const float*)d_in[11];
    const float* g_p    = (const float*)d_in[12];
    const float* b_p    = (const float*)d_in[13];
    const float* m_p    = (const float*)d_in[14];
    const float* v_p    = (const float*)d_in[15];
    const float* w_c1   = (const float*)d_in[16];
    const float* g_c1   = (const float*)d_in[17];
    const float* b_c1   = (const float*)d_in[18];
    const float* m_c1   = (const float*)d_in[19];
    const float* v_c1   = (const float*)d_in[20];
    const float* w_c2   = (const float*)d_in[21];
    const float* g_c2   = (const float*)d_in[22];
    const float* b_c2   = (const float*)d_in[23];
    const float* m_c2   = (const float*)d_in[24];
    const float* v_c2   = (const float*)d_in[25];
    float* out = (float*)d_out;

    float *bufA, *bufB, *rmaxT, *cmaxT;
    __nv_bfloat16 *pxh, *pxl, *pth, *ptl, *bl1, *blP, *blC2, *blC1;
    cudaGetSymbolAddress((void**)&bufA,  g_bufA);
    cudaGetSymbolAddress((void**)&bufB,  g_bufB);
    cudaGetSymbolAddress((void**)&rmaxT, g_rmaxT);
    cudaGetSymbolAddress((void**)&cmaxT, g_cmaxT);
    cudaGetSymbolAddress((void**)&pxh,   g_pxh);
    cudaGetSymbolAddress((void**)&pxl,   g_pxl);
    cudaGetSymbolAddress((void**)&pth,   g_pth);
    cudaGetSymbolAddress((void**)&ptl,   g_ptl);
    cudaGetSymbolAddress((void**)&bl1,   g_blob1);
    cudaGetSymbolAddress((void**)&blP,   g_blobP);
    cudaGetSymbolAddress((void**)&blC2,  g_blobC2);
    cudaGetSymbolAddress((void**)&blC1,  g_blobC1);

    cudaFuncSetAttribute(conv_mma<0>, cudaFuncAttributeMaxDynamicSharedMemorySize, CONV_SMEM);
    cudaFuncSetAttribute(conv_mma<1>, cudaFuncAttributeMaxDynamicSharedMemorySize, CONV_SMEM);
    cudaFuncSetAttribute(conv_mma<2>, cudaFuncAttributeMaxDynamicSharedMemorySize, CONV_SMEM);
    cudaFuncSetAttribute(conv_mma<3>, cudaFuncAttributeMaxDynamicSharedMemorySize, CONV_SMEM);

    // totals = images * 8192
    prepack_kernel<<<1179648/256, 256>>>(w_up, w_down, 2, 9, bl1, 1179648);
    prepack_kernel<<<589824/256,  256>>>(w_p,  w_p,    2, 9, blP, 589824);
    prepack_kernel<<<589824/256,  256>>>(w_c2, w_c2,   2, 9, blC2, 589824);
    prepack_kernel<<<65536/256,   256>>>(w_c1, w_c1,   2, 1, blC1, 65536);
    zero_border_kernel<<<(4*516*256)/256, 256>>>(pxh, pxl, pth, ptl);
    pad_convert_kernel<<<dim3(4,128,4), 256>>>(x, pxh, pxl);

    // fused up+down: z0,1 -> rowmaxT; z2,3 -> down relu map in bufA
    conv_mma<0><<<dim3(HH,BBATCH,4), 256, CONV_SMEM>>>(pxh, pxl, bl1,
        g_up, b_up, m_up, v_up, g_down, b_down, m_down, v_down,
        nullptr, rmaxT, bufA);
    colmaxT_kernel<<<512, 256>>>(bufA, cmaxT);
    sbuild_kernel<<<dim3(128,128,4), 256>>>(rmaxT, cmaxT, pth, ptl);

    // bn1 = BN(conv1x1(x)) -> bufB
    conv_mma<3><<<dim3(HH,BBATCH,2), 256, CONV_SMEM>>>(pxh, pxl, blC1,
        g_c1, b_c1, m_c1, v_c1, g_c1, b_c1, m_c1, v_c1,
        nullptr, bufB, nullptr);

    // relu1 = relu(BN(conv_p(S)) + bn1) -> bufA
    conv_mma<1><<<dim3(HH,BBATCH,2), 256, CONV_SMEM>>>(pth, ptl, blP,
        g_p, b_p, m_p, v_p, g_p, b_p, m_p, v_p,
        bufB, bufA, nullptr);

    pad_convert_kernel<<<dim3(4,128,4), 256>>>(bufA, pth, ptl);

    // out = CBR(relu1, w_c2)
    conv_mma<2><<<dim3(HH,BBATCH,2), 256, CONV_SMEM>>>(pth, ptl, blC2,
        g_c2, b_c2, m_c2, v_c2, g_c2, b_c2, m_c2, v_c2,
        nullptr, out, nullptr);
}

// round 9
// speedup vs baseline: 3.3991x; 1.1091x over previous
#include <cuda_runtime.h>
#include <cuda_bf16.h>
#include <math.h>
#include <float.h>
#include <stdint.h>

#define BBATCH 4
#define CCH 256
#define HH 128
#define WWD 128
#define HW (HH*WWD)
#define CHW (CCH*HW)
#define TOTN (BBATCH*CHW)
#define PH 130
#define PSZ (PH*PH)
#define PADTOT (BBATCH*PSZ*CCH)

// ---------------- device scratch ----------------
__device__ __align__(256) float g_bufA[TOTN];
__device__ __align__(256) float g_bufB[TOTN];
__device__ __align__(256) __nv_bfloat16 g_pxh[PADTOT];
__device__ __align__(256) __nv_bfloat16 g_pxl[PADTOT];
__device__ __align__(256) __nv_bfloat16 g_pth[PADTOT];
__device__ __align__(256) __nv_bfloat16 g_ptl[PADTOT];
__device__ __align__(256) float g_rmaxT[BBATCH*HH*CCH];   // [b][h][c]
__device__ __align__(256) float g_cmaxT[BBATCH*WWD*CCH];  // [b][w][c]
__device__ __align__(256) __nv_bfloat16 g_blob1[4*4*9*16384];
__device__ __align__(256) __nv_bfloat16 g_blobP[2*4*9*16384];
__device__ __align__(256) __nv_bfloat16 g_blobC2[2*4*9*16384];
__device__ __align__(256) __nv_bfloat16 g_blobC1[2*4*1*16384];

// ---------------- PTX helpers (plain sm_100 legal) ----------------
__device__ __forceinline__ uint32_t cvta_smem(const void* p) {
    uint32_t a;
    asm("{ .reg .u64 t; cvta.to.shared.u64 t, %1; cvt.u32.u64 %0, t; }" : "=r"(a) : "l"(p));
    return a;
}
__device__ __forceinline__ void cpa16(uint32_t s, const void* g) {
    asm volatile("{ .reg .u64 ga; cvta.to.global.u64 ga, %1; cp.async.cg.shared.global [%0], [ga], 16; }"
        :: "r"(s), "l"(g) : "memory");
}
#define CP_COMMIT() asm volatile("cp.async.commit_group;" ::: "memory")
#define CP_WAIT(n)  asm volatile("cp.async.wait_group %0;" :: "n"(n) : "memory")

__device__ __forceinline__ void ldsm4(uint32_t* r, uint32_t addr) {
    asm volatile("ldmatrix.sync.aligned.m8n8.x4.shared.b16 {%0,%1,%2,%3}, [%4];"
        : "=r"(r[0]), "=r"(r[1]), "=r"(r[2]), "=r"(r[3]) : "r"(addr));
}
__device__ __forceinline__ void mma16816(float* c, const uint32_t* a, const uint32_t* b) {
    asm volatile("mma.sync.aligned.m16n8k16.row.col.f32.bf16.bf16.f32 "
        "{%0,%1,%2,%3}, {%4,%5,%6,%7}, {%8,%9}, {%0,%1,%2,%3};"
        : "+f"(c[0]), "+f"(c[1]), "+f"(c[2]), "+f"(c[3])
        : "r"(a[0]), "r"(a[1]), "r"(a[2]), "r"(a[3]), "r"(b[0]), "r"(b[1]));
}

// ---------------- mma.sync conv, 2 CTAs/SM ----------------
// SMEM: Wbuf0 @0 (32K: hi16K+lo16K) | Wbuf1 @32768 | B @65536 single buffer
//       (33280: hi 130*128 + lo) | rsm @98816. Total 99328 -> 2 CTAs/SM.
// B staged once per (chunk,dy); dx via ldmatrix row offset (+dx+1).
#define CONV_SMEM 99328
template<int EPI>
__global__ __launch_bounds__(256, 2) void conv_mma(
    const __nv_bfloat16* __restrict__ in_hi, const __nv_bfloat16* __restrict__ in_lo,
    const __nv_bfloat16* __restrict__ wblob,
    const float* __restrict__ gA, const float* __restrict__ bA,
    const float* __restrict__ mA, const float* __restrict__ vA,
    const float* __restrict__ gB, const float* __restrict__ bB,
    const float* __restrict__ mB, const float* __restrict__ vB,
    const float* __restrict__ aux, float* __restrict__ out0, float* __restrict__ out1)
{
    constexpr int NSH   = (EPI == 3) ? 1 : 9;
    constexpr int NSTEP = 4 * NSH;
    constexpr int BSP   = (EPI == 3) ? 1 : 3;   // steps per B stage
    extern __shared__ char smem[];
    const uint32_t sb = cvta_smem(smem);
    float* rsm = (float*)(smem + 98816);

    const int tid  = threadIdx.x;
    const int h    = blockIdx.x;
    const int b    = blockIdx.y;
    const int z    = blockIdx.z;
    const int lane = tid & 31;
    const int wid  = tid >> 5;
    const int warp_m = wid >> 2;   // 0..1 (64 oc each)
    const int warp_n = wid & 3;    // 0..3 (32 px each)
    const int lrow = lane & 15;
    const int lcol = lane >> 4;

    if (EPI == 0 && z < 2 && tid < 128) rsm[tid] = 0.f;

    float c[4][4][4];
#pragma unroll
    for (int i = 0; i < 4; ++i)
#pragma unroll
        for (int j = 0; j < 4; ++j)
#pragma unroll
            for (int r = 0; r < 4; ++r) c[i][j][r] = 0.f;

    const size_t inb = (size_t)b * PSZ * CCH;

    auto stage_w = [&](int s) {
        const uint32_t base = sb + (uint32_t)(s & 1) * 32768;
        const char* asrc = (const char*)wblob + (size_t)((z * 4 + s / NSH) * NSH + (s % NSH)) * 32768;
#pragma unroll
        for (int t = 0; t < 8; ++t) {
            int i = tid + t * 256;
            cpa16(base + i * 16, asrc + i * 16);
        }
    };
    auto stage_b = [&](int sid) {
        const int chunk = (EPI == 3) ? sid : sid / 3;
        const int dy    = (EPI == 3) ? 0   : sid % 3 - 1;
        const uint32_t base = sb + 65536;
        const __nv_bfloat16* bh = in_hi + inb + (size_t)(h + dy + 1) * PH * CCH + chunk * 64;
        const __nv_bfloat16* bl = in_lo + inb + (size_t)(h + dy + 1) * PH * CCH + chunk * 64;
        for (int i = tid; i < 1040; i += 256) {       // 130 rows x 8 kc
            int wp = i >> 3;
            int kc = i & 7;
            uint32_t dst = base + wp * 128 + ((kc ^ (wp & 7)) * 16);
            cpa16(dst,         bh + (size_t)wp * CCH + kc * 8);
            cpa16(dst + 16640, bl + (size_t)wp * CCH + kc * 8);
        }
    };

    stage_w(0);
    stage_b(0);
    CP_COMMIT();

    for (int s = 0; s < NSTEP; ++s) {
        if (s > 0 && s % BSP == 0) { stage_b(s / BSP); CP_COMMIT(); }
        if (s + 1 < NSTEP) { stage_w(s + 1); CP_COMMIT(); CP_WAIT(1); }
        else               { CP_WAIT(0); }
        __syncthreads();

        const uint32_t Ahi = sb + (uint32_t)(s & 1) * 32768;
        const uint32_t Alo = Ahi + 16384;
        const uint32_t Bhi = sb + 65536;
        const uint32_t Blo = Bhi + 16640;
        const int dxp = (EPI == 3) ? 1 : (s % 3);   // dx+1 in {0,1,2}

#pragma unroll
        for (int kk = 0; kk < 4; ++kk) {
            const int kc = kk * 2 + lcol;
            uint32_t a[4][4], b1[4][2], b2[4][2];
            // A-hi fragments
#pragma unroll
            for (int i = 0; i < 4; ++i) {
                int row = warp_m * 64 + i * 16 + lrow;
                ldsm4(a[i], Ahi + (uint32_t)(row * 128 + ((kc ^ (row & 7)) * 16)));
            }
            // B-hi fragments
#pragma unroll
            for (int j = 0; j < 2; ++j) {
                int row = warp_n * 32 + j * 16 + lrow + dxp;
                uint32_t q[4];
                ldsm4(q, Bhi + (uint32_t)(row * 128 + ((kc ^ (row & 7)) * 16)));
                b1[j * 2 + 0][0] = q[0]; b1[j * 2 + 0][1] = q[2];
                b1[j * 2 + 1][0] = q[1]; b1[j * 2 + 1][1] = q[3];
            }
#pragma unroll
            for (int i = 0; i < 4; ++i)
#pragma unroll
                for (int j = 0; j < 4; ++j) mma16816(c[i][j], a[i], b1[j]);
            // B-lo fragments
#pragma unroll
            for (int j = 0; j < 2; ++j) {
                int row = warp_n * 32 + j * 16 + lrow + dxp;
                uint32_t q[4];
                ldsm4(q, Blo + (uint32_t)(row * 128 + ((kc ^ (row & 7)) * 16)));
                b2[j * 2 + 0][0] = q[0]; b2[j * 2 + 0][1] = q[2];
                b2[j * 2 + 1][0] = q[1]; b2[j * 2 + 1][1] = q[3];
            }
#pragma unroll
            for (int i = 0; i < 4; ++i)
#pragma unroll
                for (int j = 0; j < 4; ++j) mma16816(c[i][j], a[i], b2[j]);
            // A-lo fragments (reuse a[] registers)
#pragma unroll
            for (int i = 0; i < 4; ++i) {
                int row = warp_m * 64 + i * 16 + lrow;
                ldsm4(a[i], Alo + (uint32_t)(row * 128 + ((kc ^ (row & 7)) * 16)));
            }
#pragma unroll
            for (int i = 0; i < 4; ++i)
#pragma unroll
                for (int j = 0; j < 4; ++j) mma16816(c[i][j], a[i], b1[j]);
        }
        __syncthreads();
    }

    // ---- epilogue ----
    const int quad = lane >> 2;
    const int tq   = lane & 3;
    const int ocb  = (EPI == 0) ? (z & 1) * 128 : z * 128;
    const bool up  = (EPI == 0) && (z < 2);
    const float* gp = (EPI == 0 && z >= 2) ? gB : gA;
    const float* bp = (EPI == 0 && z >= 2) ? bB : bA;
    const float* mp = (EPI == 0 && z >= 2) ? mB : mA;
    const float* vp = (EPI == 0 && z >= 2) ? vB : vA;

#pragma unroll
    for (int i = 0; i < 4; ++i) {
#pragma unroll
        for (int h2 = 0; h2 < 2; ++h2) {
            const int ocl = warp_m * 64 + i * 16 + quad + h2 * 8;
            const int oc  = ocb + ocl;
            const float sc = gp[oc] * rsqrtf(vp[oc] + 1e-5f);
            const float sh = bp[oc] - mp[oc] * sc;
            if (up) {
                float m = 0.f;
#pragma unroll
                for (int j = 0; j < 4; ++j) {
                    m = fmaxf(m, c[i][j][h2 * 2 + 0] * sc + sh);
                    m = fmaxf(m, c[i][j][h2 * 2 + 1] * sc + sh);
                }
                atomicMax((unsigned*)&rsm[ocl], __float_as_uint(fmaxf(m, 0.f)));
            } else {
                size_t rowbase = ((size_t)b * CCH + oc) * HW + (size_t)h * WWD;
#pragma unroll
                for (int j = 0; j < 4; ++j) {
                    const int w = warp_n * 32 + j * 8 + tq * 2;
                    float v0 = c[i][j][h2 * 2 + 0] * sc + sh;
                    float v1 = c[i][j][h2 * 2 + 1] * sc + sh;
                    if (EPI == 1) {
                        float2 a2 = *(const float2*)(aux + rowbase + w);
                        v0 = fmaxf(v0 + a2.x, 0.f);
                        v1 = fmaxf(v1 + a2.y, 0.f);
                        *(float2*)(out0 + rowbase + w) = make_float2(v0, v1);
                    } else if (EPI == 3) {
                        *(float2*)(out0 + rowbase + w) = make_float2(v0, v1);
                    } else {
                        float* dst = (EPI == 0) ? out1 : out0;
                        *(float2*)(dst + rowbase + w) = make_float2(fmaxf(v0, 0.f), fmaxf(v1, 0.f));
                    }
                }
            }
        }
    }
    if (up) {
        __syncthreads();
        if (tid < 128)
            out0[((size_t)b * HH + h) * CCH + z * 128 + tid] = rsm[tid];
    }
}

// ---------------- weight prepack: one thread per (image, ocl, icl); total = images*8192 ----------------
__global__ void prepack_kernel(const float* __restrict__ srcA, const float* __restrict__ srcB,
                               int zsplit, int NSH, __nv_bfloat16* __restrict__ blob, int total)
{
    int idx = blockIdx.x * 256 + threadIdx.x;
    if (idx >= total) return;
    int icl  = idx & 63;
    int ocl  = (idx >> 6) & 127;
    int rest = idx >> 13;
    int r = rest % NSH; rest /= NSH;
    int chunk = rest & 3;
    int zz    = rest >> 2;
    const float* src = srcA;
    int o = zz * 128 + ocl;
    if (zz >= zsplit) { src = srcB; o = (zz - zsplit) * 128 + ocl; }
    int ic = chunk * 64 + icl;
    float w = src[(size_t)(o * 256 + ic) * NSH + r];
    __nv_bfloat16 hi = __float2bfloat16_rn(w);
    __nv_bfloat16 lo = __float2bfloat16_rn(w - __bfloat162float(hi));
    size_t base = (size_t)((zz * 4 + chunk) * NSH + r) * 16384;
    uint32_t off = (uint32_t)(ocl * 64 + (((icl >> 3) ^ (ocl & 7)) * 8) + (icl & 7));
    blob[base + off]        = hi;
    blob[base + 8192 + off] = lo;
}

// ---------------- zero borders of the 4 padded buffers ----------------
__global__ void zero_border_kernel(__nv_bfloat16* a, __nv_bfloat16* b,
                                   __nv_bfloat16* c, __nv_bfloat16* d) {
    int idx = blockIdx.x * 256 + threadIdx.x;   // 4*516*256
    int ch   = idx & 255;
    int rest = idx >> 8;
    int p    = rest % 516;
    int bb   = rest / 516;
    int h, w;
    if (p < 260) { h = (p < 130) ? 0 : 129; w = p % 130; }
    else         { int q = p - 260; h = 1 + (q & 127); w = (q >> 7) * 129; }
    size_t i = ((size_t)bb * PSZ + (size_t)h * PH + w) * CCH + ch;
    a[i] = __float2bfloat16(0.f); b[i] = __float2bfloat16(0.f);
    c[i] = __float2bfloat16(0.f); d[i] = __float2bfloat16(0.f);
}

// ---------------- fp32 NCHW -> padded [h][w][c] bf16 hi/lo ----------------
__global__ void pad_convert_kernel(const float* __restrict__ src,
                                   __nv_bfloat16* __restrict__ phb,
                                   __nv_bfloat16* __restrict__ plb)
{
    __shared__ float s[256][33];
    const int w0 = blockIdx.x * 32;
    const int h  = blockIdx.y;
    const int b  = blockIdx.z;
    const int tid = threadIdx.x;
    const int wl8 = tid & 31;
#pragma unroll 4
    for (int i = 0; i < 32; ++i) {
        int c = i * 8 + (tid >> 5);
        s[c][wl8] = src[((size_t)(b * CCH + c) * HH + h) * WWD + w0 + wl8];
    }
    __syncthreads();
    const int wl = tid >> 3;
    const int cg = (tid & 7) * 32;
    __align__(16) __nv_bfloat16 hi[32];
    __align__(16) __nv_bfloat16 lo[32];
#pragma unroll
    for (int j = 0; j < 32; ++j) {
        float v = s[cg + j][wl];
        hi[j] = __float2bfloat16_rn(v);
        lo[j] = __float2bfloat16_rn(v - __bfloat162float(hi[j]));
    }
    size_t base = ((size_t)b * PSZ + (size_t)(h + 1) * PH + (w0 + wl + 1)) * CCH + cg;
    uint4* hp = (uint4*)(phb + base);
    uint4* lp = (uint4*)(plb + base);
    const uint4* hs = (const uint4*)hi;
    const uint4* ls = (const uint4*)lo;
#pragma unroll
    for (int q = 0; q < 4; ++q) { hp[q] = hs[q]; lp[q] = ls[q]; }
}

// ---------------- column max over H (NCHW in) -> [b][w][c] ----------------
__global__ void colmaxT_kernel(const float* __restrict__ in, float* __restrict__ outT) {
    int idx = blockIdx.x * 256 + threadIdx.x;   // (b*256+oc)*128 + w
    int w  = idx & 127;
    int bc = idx >> 7;
    int oc = bc & 255;
    int b  = bc >> 8;
    const float* p = in + (size_t)bc * HW + w;
    float m = -FLT_MAX;
#pragma unroll 4
    for (int h = 0; h < HH; ++h) m = fmaxf(m, p[(size_t)h * WWD]);
    outT[((size_t)b * WWD + w) * CCH + oc] = m;
}

// ---------------- S = rmax + cmax -> padded bf16 hi/lo ----------------
__global__ void sbuild_kernel(const float* __restrict__ rT, const float* __restrict__ cT,
                              __nv_bfloat16* __restrict__ phb, __nv_bfloat16* __restrict__ plb)
{
    const int w = blockIdx.x, h = blockIdx.y, b = blockIdx.z;
    const int c = threadIdx.x;
    float v = rT[((size_t)b * HH + h) * CCH + c] + cT[((size_t)b * WWD + w) * CCH + c];
    __nv_bfloat16 hi = __float2bfloat16_rn(v);
    __nv_bfloat16 lo = __float2bfloat16_rn(v - __bfloat162float(hi));
    size_t idx = ((size_t)b * PSZ + (size_t)(h + 1) * PH + (w + 1)) * CCH + c;
    phb[idx] = hi;
    plb[idx] = lo;
}

// ---------------- launch ----------------
extern "C" void kernel_launch(void* const* d_in, const int* in_sizes, int n_in,
                              void* d_out, int out_size) {
    (void)in_sizes; (void)n_in; (void)out_size;
    const float* x      = (const float*)d_in[0];
    const float* w_up   = (const float*)d_in[1];
    const float* g_up   = (const float*)d_in[2];
    const float* b_up   = (const float*)d_in[3];
    const float* m_up   = (const float*)d_in[4];
    const float* v_up   = (const float*)d_in[5];
    const float* w_down = (const float*)d_in[6];
    const float* g_down = (const float*)d_in[7];
    const float* b_down = (const float*)d_in[8];
    const float* m_down = (const float*)d_in[9];
    const float* v_down = (const float*)d_in[10];
    const float* w_p    = (const float*)d_in[11];
    const float* g_p    = (const float*)d_in[12];
    const float* b_p    = (const float*)d_in[13];
    const float* m_p    = (const float*)d_in[14];
    const float* v_p    = (const float*)d_in[15];
    const float* w_c1   = (const float*)d_in[16];
    const float* g_c1   = (const float*)d_in[17];
    const float* b_c1   = (const float*)d_in[18];
    const float* m_c1   = (const float*)d_in[19];
    const float* v_c1   = (const float*)d_in[20];
    const float* w_c2   = (const float*)d_in[21];
    const float* g_c2   = (const float*)d_in[22];
    const float* b_c2   = (const float*)d_in[23];
    const float* m_c2   = (const float*)d_in[24];
    const float* v_c2   = (const float*)d_in[25];
    float* out = (float*)d_out;

    float *bufA, *bufB, *rmaxT, *cmaxT;
    __nv_bfloat16 *pxh, *pxl, *pth, *ptl, *bl1, *blP, *blC2, *blC1;
    cudaGetSymbolAddress((void**)&bufA,  g_bufA);
    cudaGetSymbolAddress((void**)&bufB,  g_bufB);
    cudaGetSymbolAddress((void**)&rmaxT, g_rmaxT);
    cudaGetSymbolAddress((void**)&cmaxT, g_cmaxT);
    cudaGetSymbolAddress((void**)&pxh,   g_pxh);
    cudaGetSymbolAddress((void**)&pxl,   g_pxl);
    cudaGetSymbolAddress((void**)&pth,   g_pth);
    cudaGetSymbolAddress((void**)&ptl,   g_ptl);
    cudaGetSymbolAddress((void**)&bl1,   g_blob1);
    cudaGetSymbolAddress((void**)&blP,   g_blobP);
    cudaGetSymbolAddress((void**)&blC2,  g_blobC2);
    cudaGetSymbolAddress((void**)&blC1,  g_blobC1);

    cudaFuncSetAttribute(conv_mma<0>, cudaFuncAttributeMaxDynamicSharedMemorySize, CONV_SMEM);
    cudaFuncSetAttribute(conv_mma<1>, cudaFuncAttributeMaxDynamicSharedMemorySize, CONV_SMEM);
    cudaFuncSetAttribute(conv_mma<2>, cudaFuncAttributeMaxDynamicSharedMemorySize, CONV_SMEM);
    cudaFuncSetAttribute(conv_mma<3>, cudaFuncAttributeMaxDynamicSharedMemorySize, CONV_SMEM);

    // totals = images * 8192
    prepack_kernel<<<1179648/256, 256>>>(w_up, w_down, 2, 9, bl1, 1179648);
    prepack_kernel<<<589824/256,  256>>>(w_p,  w_p,    2, 9, blP, 589824);
    prepack_kernel<<<589824/256,  256>>>(w_c2, w_c2,   2, 9, blC2, 589824);
    prepack_kernel<<<65536/256,   256>>>(w_c1, w_c1,   2, 1, blC1, 65536);
    zero_border_kernel<<<(4*516*256)/256, 256>>>(pxh, pxl, pth, ptl);
    pad_convert_kernel<<<dim3(4,128,4), 256>>>(x, pxh, pxl);

    // fused up+down: z0,1 -> rowmaxT; z2,3 -> down relu map in bufA
    conv_mma<0><<<dim3(HH,BBATCH,4), 256, CONV_SMEM>>>(pxh, pxl, bl1,
        g_up, b_up, m_up, v_up, g_down, b_down, m_down, v_down,
        nullptr, rmaxT, bufA);
    colmaxT_kernel<<<512, 256>>>(bufA, cmaxT);
    sbuild_kernel<<<dim3(128,128,4), 256>>>(rmaxT, cmaxT, pth, ptl);

    // bn1 = BN(conv1x1(x)) -> bufB
    conv_mma<3><<<dim3(HH,BBATCH,2), 256, CONV_SMEM>>>(pxh, pxl, blC1,
        g_c1, b_c1, m_c1, v_c1, g_c1, b_c1, m_c1, v_c1,
        nullptr, bufB, nullptr);

    // relu1 = relu(BN(conv_p(S)) + bn1) -> bufA
    conv_mma<1><<<dim3(HH,BBATCH,2), 256, CONV_SMEM>>>(pth, ptl, blP,
        g_p, b_p, m_p, v_p, g_p, b_p, m_p, v_p,
        bufB, bufA, nullptr);

    pad_convert_kernel<<<dim3(4,128,4), 256>>>(bufA, pth, ptl);

    // out = CBR(relu1, w_c2)
    conv_mma<2><<<dim3(HH,BBATCH,2), 256, CONV_SMEM>>>(pth, ptl, blC2,
        g_c2, b_c2, m_c2, v_c2, g_c2, b_c2, m_c2, v_c2,
        nullptr, out, nullptr);
}

// round 10
// speedup vs baseline: 7.8900x; 2.3212x over previous
#include <cuda_runtime.h>
#include <cuda_fp16.h>
#include <math.h>
#include <float.h>
#include <stdint.h>

#define BBATCH 4
#define CCH 256
#define HH 128
#define WWD 128
#define HW (HH*WWD)
#define CHW (CCH*HW)
#define TOTN (BBATCH*CHW)
#define PH 130
#define PSZ (PH*PH)
#define PADTOT (BBATCH*PSZ*CCH)

// ---------------- device scratch ----------------
__device__ __align__(256) float g_bufA[TOTN];
__device__ __align__(256) float g_bufB[TOTN];
__device__ __align__(256) __half g_px[PADTOT];            // padded x, fp16
__device__ __align__(256) __half g_pt[PADTOT];            // padded temp (S, relu1)
__device__ __align__(256) float g_rmaxT[BBATCH*HH*CCH];   // [b][h][c]
__device__ __align__(256) float g_cmaxT[BBATCH*WWD*CCH];  // [b][w][c]
__device__ __align__(256) __half g_blob1[4*4*9*8192];
__device__ __align__(256) __half g_blobP[2*4*9*8192];
__device__ __align__(256) __half g_blobC2[2*4*9*8192];
__device__ __align__(256) __half g_blobC1[2*4*1*8192];

// ---------------- PTX helpers (plain sm_100 legal) ----------------
__device__ __forceinline__ uint32_t cvta_smem(const void* p) {
    uint32_t a;
    asm("{ .reg .u64 t; cvta.to.shared.u64 t, %1; cvt.u32.u64 %0, t; }" : "=r"(a) : "l"(p));
    return a;
}
__device__ __forceinline__ void cpa16(uint32_t s, const void* g) {
    asm volatile("{ .reg .u64 ga; cvta.to.global.u64 ga, %1; cp.async.cg.shared.global [%0], [ga], 16; }"
        :: "r"(s), "l"(g) : "memory");
}
#define CP_COMMIT() asm volatile("cp.async.commit_group;" ::: "memory")
#define CP_WAIT(n)  asm volatile("cp.async.wait_group %0;" :: "n"(n) : "memory")

__device__ __forceinline__ void ldsm4(uint32_t* r, uint32_t addr) {
    asm volatile("ldmatrix.sync.aligned.m8n8.x4.shared.b16 {%0,%1,%2,%3}, [%4];"
        : "=r"(r[0]), "=r"(r[1]), "=r"(r[2]), "=r"(r[3]) : "r"(addr));
}
__device__ __forceinline__ void mma16816(float* c, const uint32_t* a, const uint32_t* b) {
    asm volatile("mma.sync.aligned.m16n8k16.row.col.f32.f16.f16.f32 "
        "{%0,%1,%2,%3}, {%4,%5,%6,%7}, {%8,%9}, {%0,%1,%2,%3};"
        : "+f"(c[0]), "+f"(c[1]), "+f"(c[2]), "+f"(c[3])
        : "r"(a[0]), "r"(a[1]), "r"(a[2]), "r"(a[3]), "r"(b[0]), "r"(b[1]));
}

// ---------------- mma.sync fp16 conv ----------------
// SMEM: W0 @0 (16K) | W1 @16384 | B @32768 (16640 = 130 rows x 128B, single buffer)
//       | rsm @49408. Total 49920 -> 2 CTAs/SM (reg-bound).
// B staged once per (chunk,dy); dx via ldmatrix row offset (+dx+1).
#define CONV_SMEM 49920
template<int EPI>
__global__ __launch_bounds__(256, 2) void conv_mma(
    const __half* __restrict__ in, const __half* __restrict__ wblob,
    const float* __restrict__ gA, const float* __restrict__ bA,
    const float* __restrict__ mA, const float* __restrict__ vA,
    const float* __restrict__ gB, const float* __restrict__ bB,
    const float* __restrict__ mB, const float* __restrict__ vB,
    const float* __restrict__ aux, float* __restrict__ out0, float* __restrict__ out1)
{
    constexpr int NSH   = (EPI == 3) ? 1 : 9;
    constexpr int NSTEP = 4 * NSH;
    constexpr int BSP   = (EPI == 3) ? 1 : 3;   // steps per B stage
    extern __shared__ char smem[];
    const uint32_t sb = cvta_smem(smem);
    float* rsm = (float*)(smem + 49408);

    const int tid  = threadIdx.x;
    const int h    = blockIdx.x;
    const int b    = blockIdx.y;
    const int z    = blockIdx.z;
    const int lane = tid & 31;
    const int wid  = tid >> 5;
    const int warp_m = wid >> 2;   // 0..1 (64 oc each)
    const int warp_n = wid & 3;    // 0..3 (32 px each)
    const int lrow = lane & 15;
    const int lcol = lane >> 4;

    if (EPI == 0 && z < 2 && tid < 128) rsm[tid] = 0.f;

    float c[4][4][4];
#pragma unroll
    for (int i = 0; i < 4; ++i)
#pragma unroll
        for (int j = 0; j < 4; ++j)
#pragma unroll
            for (int r = 0; r < 4; ++r) c[i][j][r] = 0.f;

    const size_t inb = (size_t)b * PSZ * CCH;

    auto stage_w = [&](int s) {
        const uint32_t base = sb + (uint32_t)(s & 1) * 16384;
        const char* asrc = (const char*)wblob + (size_t)((z * 4 + s / NSH) * NSH + (s % NSH)) * 16384;
#pragma unroll
        for (int t = 0; t < 4; ++t) {
            int i = tid + t * 256;
            cpa16(base + i * 16, asrc + i * 16);
        }
    };
    auto stage_b = [&](int sid) {
        const int chunk = (EPI == 3) ? sid : sid / 3;
        const int dy    = (EPI == 3) ? 0   : sid % 3 - 1;
        const uint32_t base = sb + 32768;
        const __half* bp = in + inb + (size_t)(h + dy + 1) * PH * CCH + chunk * 64;
        for (int i = tid; i < 1040; i += 256) {       // 130 rows x 8 kc
            int wp = i >> 3;
            int kc = i & 7;
            cpa16(base + wp * 128 + ((kc ^ (wp & 7)) * 16), bp + (size_t)wp * CCH + kc * 8);
        }
    };

    stage_w(0);
    stage_b(0);
    CP_COMMIT();

    for (int s = 0; s < NSTEP; ++s) {
        if (s > 0 && s % BSP == 0) { stage_b(s / BSP); CP_COMMIT(); }
        if (s + 1 < NSTEP) { stage_w(s + 1); CP_COMMIT(); CP_WAIT(1); }
        else               { CP_WAIT(0); }
        __syncthreads();

        const uint32_t Ab = sb + (uint32_t)(s & 1) * 16384;
        const uint32_t Bb = sb + 32768;
        const int dxp = (EPI == 3) ? 1 : (s % 3);   // dx+1 in {0,1,2}

#pragma unroll
        for (int kk = 0; kk < 4; ++kk) {
            const int kc = kk * 2 + lcol;
            uint32_t a[4][4], bbf[4][2];
#pragma unroll
            for (int i = 0; i < 4; ++i) {
                int row = warp_m * 64 + i * 16 + lrow;
                ldsm4(a[i], Ab + (uint32_t)(row * 128 + ((kc ^ (row & 7)) * 16)));
            }
#pragma unroll
            for (int j = 0; j < 2; ++j) {
                int row = warp_n * 32 + j * 16 + lrow + dxp;
                uint32_t q[4];
                ldsm4(q, Bb + (uint32_t)(row * 128 + ((kc ^ (row & 7)) * 16)));
                bbf[j * 2 + 0][0] = q[0]; bbf[j * 2 + 0][1] = q[2];
                bbf[j * 2 + 1][0] = q[1]; bbf[j * 2 + 1][1] = q[3];
            }
#pragma unroll
            for (int i = 0; i < 4; ++i)
#pragma unroll
                for (int j = 0; j < 4; ++j) mma16816(c[i][j], a[i], bbf[j]);
        }
        __syncthreads();
    }

    // ---- epilogue ----
    const int quad = lane >> 2;
    const int tq   = lane & 3;
    const int ocb  = (EPI == 0) ? (z & 1) * 128 : z * 128;
    const bool up  = (EPI == 0) && (z < 2);
    const float* gp = (EPI == 0 && z >= 2) ? gB : gA;
    const float* bp = (EPI == 0 && z >= 2) ? bB : bA;
    const float* mp = (EPI == 0 && z >= 2) ? mB : mA;
    const float* vp = (EPI == 0 && z >= 2) ? vB : vA;

#pragma unroll
    for (int i = 0; i < 4; ++i) {
#pragma unroll
        for (int h2 = 0; h2 < 2; ++h2) {
            const int ocl = warp_m * 64 + i * 16 + quad + h2 * 8;
            const int oc  = ocb + ocl;
            const float sc = gp[oc] * rsqrtf(vp[oc] + 1e-5f);
            const float sh = bp[oc] - mp[oc] * sc;
            if (up) {
                float m = 0.f;
#pragma unroll
                for (int j = 0; j < 4; ++j) {
                    m = fmaxf(m, c[i][j][h2 * 2 + 0] * sc + sh);
                    m = fmaxf(m, c[i][j][h2 * 2 + 1] * sc + sh);
                }
                atomicMax((unsigned*)&rsm[ocl], __float_as_uint(fmaxf(m, 0.f)));
            } else {
                size_t rowbase = ((size_t)b * CCH + oc) * HW + (size_t)h * WWD;
#pragma unroll
                for (int j = 0; j < 4; ++j) {
                    const int w = warp_n * 32 + j * 8 + tq * 2;
                    float v0 = c[i][j][h2 * 2 + 0] * sc + sh;
                    float v1 = c[i][j][h2 * 2 + 1] * sc + sh;
                    if (EPI == 1) {
                        float2 a2 = *(const float2*)(aux + rowbase + w);
                        v0 = fmaxf(v0 + a2.x, 0.f);
                        v1 = fmaxf(v1 + a2.y, 0.f);
                        *(float2*)(out0 + rowbase + w) = make_float2(v0, v1);
                    } else if (EPI == 3) {
                        *(float2*)(out0 + rowbase + w) = make_float2(v0, v1);
                    } else {
                        float* dst = (EPI == 0) ? out1 : out0;
                        *(float2*)(dst + rowbase + w) = make_float2(fmaxf(v0, 0.f), fmaxf(v1, 0.f));
                    }
                }
            }
        }
    }
    if (up) {
        __syncthreads();
        if (tid < 128)
            out0[((size_t)b * HH + h) * CCH + z * 128 + tid] = rsm[tid];
    }
}

// ---------------- weight prepack: one thread per (image, ocl, icl); total = images*8192 ----------------
__global__ void prepack_kernel(const float* __restrict__ srcA, const float* __restrict__ srcB,
                               int zsplit, int NSH, __half* __restrict__ blob, int total)
{
    int idx = blockIdx.x * 256 + threadIdx.x;
    if (idx >= total) return;
    int icl  = idx & 63;
    int ocl  = (idx >> 6) & 127;
    int rest = idx >> 13;
    int r = rest % NSH; rest /= NSH;
    int chunk = rest & 3;
    int zz    = rest >> 2;
    const float* src = srcA;
    int o = zz * 128 + ocl;
    if (zz >= zsplit) { src = srcB; o = (zz - zsplit) * 128 + ocl; }
    int ic = chunk * 64 + icl;
    float w = src[(size_t)(o * 256 + ic) * NSH + r];
    size_t base = (size_t)((zz * 4 + chunk) * NSH + r) * 8192;
    uint32_t off = (uint32_t)(ocl * 64 + (((icl >> 3) ^ (ocl & 7)) * 8) + (icl & 7));
    blob[base + off] = __float2half_rn(w);
}

// ---------------- zero borders of the 2 padded buffers ----------------
__global__ void zero_border_kernel(__half* a, __half* b) {
    int idx = blockIdx.x * 256 + threadIdx.x;   // 4*516*256
    int ch   = idx & 255;
    int rest = idx >> 8;
    int p    = rest % 516;
    int bb   = rest / 516;
    int h, w;
    if (p < 260) { h = (p < 130) ? 0 : 129; w = p % 130; }
    else         { int q = p - 260; h = 1 + (q & 127); w = (q >> 7) * 129; }
    size_t i = ((size_t)bb * PSZ + (size_t)h * PH + w) * CCH + ch;
    a[i] = __float2half(0.f); b[i] = __float2half(0.f);
}

// ---------------- fp32 NCHW -> padded [h][w][c] fp16 ----------------
__global__ void pad_convert_kernel(const float* __restrict__ src, __half* __restrict__ dst)
{
    __shared__ float s[256][33];
    const int w0 = blockIdx.x * 32;
    const int h  = blockIdx.y;
    const int b  = blockIdx.z;
    const int tid = threadIdx.x;
    const int wl8 = tid & 31;
#pragma unroll 4
    for (int i = 0; i < 32; ++i) {
        int c = i * 8 + (tid >> 5);
        s[c][wl8] = src[((size_t)(b * CCH + c) * HH + h) * WWD + w0 + wl8];
    }
    __syncthreads();
    const int wl = tid >> 3;
    const int cg = (tid & 7) * 32;
    __align__(16) __half v16[32];
#pragma unroll
    for (int j = 0; j < 32; ++j)
        v16[j] = __float2half_rn(s[cg + j][wl]);
    size_t base = ((size_t)b * PSZ + (size_t)(h + 1) * PH + (w0 + wl + 1)) * CCH + cg;
    uint4* dp = (uint4*)(dst + base);
    const uint4* vs = (const uint4*)v16;
#pragma unroll
    for (int q = 0; q < 4; ++q) dp[q] = vs[q];
}

// ---------------- column max over H (NCHW in) -> [b][w][c] ----------------
__global__ void colmaxT_kernel(const float* __restrict__ in, float* __restrict__ outT) {
    int idx = blockIdx.x * 256 + threadIdx.x;   // (b*256+oc)*128 + w
    int w  = idx & 127;
    int bc = idx >> 7;
    int oc = bc & 255;
    int b  = bc >> 8;
    const float* p = in + (size_t)bc * HW + w;
    float m = -FLT_MAX;
#pragma unroll 4
    for (int h = 0; h < HH; ++h) m = fmaxf(m, p[(size_t)h * WWD]);
    outT[((size_t)b * WWD + w) * CCH + oc] = m;
}

// ---------------- S = rmax + cmax -> padded fp16 ----------------
__global__ void sbuild_kernel(const float* __restrict__ rT, const float* __restrict__ cT,
                              __half* __restrict__ dst)
{
    const int w = blockIdx.x, h = blockIdx.y, b = blockIdx.z;
    const int c = threadIdx.x;
    float v = rT[((size_t)b * HH + h) * CCH + c] + cT[((size_t)b * WWD + w) * CCH + c];
    dst[((size_t)b * PSZ + (size_t)(h + 1) * PH + (w + 1)) * CCH + c] = __float2half_rn(v);
}

// ---------------- launch ----------------
extern "C" void kernel_launch(void* const* d_in, const int* in_sizes, int n_in,
                              void* d_out, int out_size) {
    (void)in_sizes; (void)n_in; (void)out_size;
    const float* x      = (const float*)d_in[0];
    const float* w_up   = (const float*)d_in[1];
    const float* g_up   = (const float*)d_in[2];
    const float* b_up   = (const float*)d_in[3];
    const float* m_up   = (const float*)d_in[4];
    const float* v_up   = (const float*)d_in[5];
    const float* w_down = (const float*)d_in[6];
    const float* g_down = (const float*)d_in[7];
    const float* b_down = (const float*)d_in[8];
    const float* m_down = (const float*)d_in[9];
    const float* v_down = (const float*)d_in[10];
    const float* w_p    = (const float*)d_in[11];
    const float* g_p    = (const float*)d_in[12];
    const float* b_p    = (const float*)d_in[13];
    const float* m_p    = (const float*)d_in[14];
    const float* v_p    = (const float*)d_in[15];
    const float* w_c1   = (const float*)d_in[16];
    const float* g_c1   = (const float*)d_in[17];
    const float* b_c1   = (const float*)d_in[18];
    const float* m_c1   = (const float*)d_in[19];
    const float* v_c1   = (const float*)d_in[20];
    const float* w_c2   = (const float*)d_in[21];
    const float* g_c2   = (const float*)d_in[22];
    const float* b_c2   = (const float*)d_in[23];
    const float* m_c2   = (const float*)d_in[24];
    const float* v_c2   = (const float*)d_in[25];
    float* out = (float*)d_out;

    float *bufA, *bufB, *rmaxT, *cmaxT;
    __half *px, *pt, *bl1, *blP, *blC2, *blC1;
    cudaGetSymbolAddress((void**)&bufA,  g_bufA);
    cudaGetSymbolAddress((void**)&bufB,  g_bufB);
    cudaGetSymbolAddress((void**)&rmaxT, g_rmaxT);
    cudaGetSymbolAddress((void**)&cmaxT, g_cmaxT);
    cudaGetSymbolAddress((void**)&px,    g_px);
    cudaGetSymbolAddress((void**)&pt,    g_pt);
    cudaGetSymbolAddress((void**)&bl1,   g_blob1);
    cudaGetSymbolAddress((void**)&blP,   g_blobP);
    cudaGetSymbolAddress((void**)&blC2,  g_blobC2);
    cudaGetSymbolAddress((void**)&blC1,  g_blobC1);

    cudaFuncSetAttribute(conv_mma<0>, cudaFuncAttributeMaxDynamicSharedMemorySize, CONV_SMEM);
    cudaFuncSetAttribute(conv_mma<1>, cudaFuncAttributeMaxDynamicSharedMemorySize, CONV_SMEM);
    cudaFuncSetAttribute(conv_mma<2>, cudaFuncAttributeMaxDynamicSharedMemorySize, CONV_SMEM);
    cudaFuncSetAttribute(conv_mma<3>, cudaFuncAttributeMaxDynamicSharedMemorySize, CONV_SMEM);

    // totals = images * 8192
    prepack_kernel<<<1179648/256, 256>>>(w_up, w_down, 2, 9, bl1, 1179648);
    prepack_kernel<<<589824/256,  256>>>(w_p,  w_p,    2, 9, blP, 589824);
    prepack_kernel<<<589824/256,  256>>>(w_c2, w_c2,   2, 9, blC2, 589824);
    prepack_kernel<<<65536/256,   256>>>(w_c1, w_c1,   2, 1, blC1, 65536);
    zero_border_kernel<<<(4*516*256)/256, 256>>>(px, pt);
    pad_convert_kernel<<<dim3(4,128,4), 256>>>(x, px);

    // fused up+down: z0,1 -> rowmaxT; z2,3 -> down relu map in bufA
    conv_mma<0><<<dim3(HH,BBATCH,4), 256, CONV_SMEM>>>(px, bl1,
        g_up, b_up, m_up, v_up, g_down, b_down, m_down, v_down,
        nullptr, rmaxT, bufA);
    colmaxT_kernel<<<512, 256>>>(bufA, cmaxT);
    sbuild_kernel<<<dim3(128,128,4), 256>>>(rmaxT, cmaxT, pt);

    // bn1 = BN(conv1x1(x)) -> bufB
    conv_mma<3><<<dim3(HH,BBATCH,2), 256, CONV_SMEM>>>(px, blC1,
        g_c1, b_c1, m_c1, v_c1, g_c1, b_c1, m_c1, v_c1,
        nullptr, bufB, nullptr);

    // relu1 = relu(BN(conv_p(S)) + bn1) -> bufA
    conv_mma<1><<<dim3(HH,BBATCH,2), 256, CONV_SMEM>>>(pt, blP,
        g_p, b_p, m_p, v_p, g_p, b_p, m_p, v_p,
        bufB, bufA, nullptr);

    pad_convert_kernel<<<dim3(4,128,4), 256>>>(bufA, pt);

    // out = CBR(relu1, w_c2)
    conv_mma<2><<<dim3(HH,BBATCH,2), 256, CONV_SMEM>>>(pt, blC2,
        g_c2, b_c2, m_c2, v_c2, g_c2, b_c2, m_c2, v_c2,
        nullptr, out, nullptr);
}

// round 11
// speedup vs baseline: 8.4107x; 1.0660x over previous
#include <cuda_runtime.h>
#include <cuda_fp16.h>
#include <math.h>
#include <float.h>
#include <stdint.h>

#define BBATCH 4
#define CCH 256
#define HH 128
#define WWD 128
#define HW (HH*WWD)
#define CHW (CCH*HW)
#define TOTN (BBATCH*CHW)
#define PH 130
#define PSZ (PH*PH)
#define PADTOT (BBATCH*PSZ*CCH)

// ---------------- device scratch ----------------
__device__ __align__(256) float g_bufA[TOTN];             // down relu map (fp32)
__device__ __align__(256) __half g_px[PADTOT];            // padded x
__device__ __align__(256) __half g_pt[PADTOT];            // padded S
__device__ __align__(256) __half g_pt2[PADTOT];           // padded relu1
__device__ __align__(256) float g_rmaxT[BBATCH*HH*CCH];   // [b][h][c]
__device__ __align__(256) float g_cmaxT[BBATCH*WWD*CCH];  // [b][w][c]
__device__ __align__(256) __half g_blob1[4*4*9*8192];
__device__ __align__(256) __half g_blobP[2*4*9*8192];
__device__ __align__(256) __half g_blobC2[2*4*9*8192];
__device__ __align__(256) __half g_blobC1[2*4*8192];

// ---------------- PTX helpers (plain sm_100 legal) ----------------
__device__ __forceinline__ uint32_t cvta_smem(const void* p) {
    uint32_t a;
    asm("{ .reg .u64 t; cvta.to.shared.u64 t, %1; cvt.u32.u64 %0, t; }" : "=r"(a) : "l"(p));
    return a;
}
__device__ __forceinline__ void cpa16(uint32_t s, const void* g) {
    asm volatile("{ .reg .u64 ga; cvta.to.global.u64 ga, %1; cp.async.cg.shared.global [%0], [ga], 16; }"
        :: "r"(s), "l"(g) : "memory");
}
#define CP_COMMIT() asm volatile("cp.async.commit_group;" ::: "memory")
#define CP_WAIT(n)  asm volatile("cp.async.wait_group %0;" :: "n"(n) : "memory")

__device__ __forceinline__ void ldsm4(uint32_t* r, uint32_t addr) {
    asm volatile("ldmatrix.sync.aligned.m8n8.x4.shared.b16 {%0,%1,%2,%3}, [%4];"
        : "=r"(r[0]), "=r"(r[1]), "=r"(r[2]), "=r"(r[3]) : "r"(addr));
}
__device__ __forceinline__ void mma16816(float* c, const uint32_t* a, const uint32_t* b) {
    asm volatile("mma.sync.aligned.m16n8k16.row.col.f32.f16.f16.f32 "
        "{%0,%1,%2,%3}, {%4,%5,%6,%7}, {%8,%9}, {%0,%1,%2,%3};"
        : "+f"(c[0]), "+f"(c[1]), "+f"(c[2]), "+f"(c[3])
        : "r"(a[0]), "r"(a[1]), "r"(a[2]), "r"(a[3]), "r"(b[0]), "r"(b[1]));
}

// ---------------- mma.sync fp16 conv (BN scale folded into weights) ----------------
// SMEM: W ring 3x16K @0 | B ring 3x16640 @49152 | rsm @99072. Total 99584 -> 2 CTAs/SM.
// One commit group per step {W(s+1) [+B(next)]}; wait_group(1); single sync/step.
// EPI 0: fused up+down (z0,1 up -> rowmax; z2,3 down -> relu map out1 fp32)
// EPI 1: conv_p(S) + conv_c1(x) fused: 36 steps from `in`(S) + 4 steps from `inx`(x);
//        epilogue relu(acc + sh_p + sh_c1) -> fp16 padded outh via SMEM bounce
// EPI 2: conv_c2: relu -> out0 fp32 (d_out)
#define CONV_SMEM 99584
template<int EPI>
__global__ __launch_bounds__(256, 2) void conv_mma(
    const __half* __restrict__ in, const __half* __restrict__ inx,
    const __half* __restrict__ wblob, const __half* __restrict__ wblob2,
    const float* __restrict__ gA, const float* __restrict__ bA,
    const float* __restrict__ mA, const float* __restrict__ vA,
    const float* __restrict__ gB, const float* __restrict__ bB,
    const float* __restrict__ mB, const float* __restrict__ vB,
    float* __restrict__ out0, float* __restrict__ out1, __half* __restrict__ outh)
{
    constexpr int NSTEP = (EPI == 1) ? 40 : 36;
    extern __shared__ char smem[];
    const uint32_t sb = cvta_smem(smem);
    float* rsm = (float*)(smem + 99072);

    const int tid  = threadIdx.x;
    const int h    = blockIdx.x;
    const int b    = blockIdx.y;
    const int z    = blockIdx.z;
    const int lane = tid & 31;
    const int wid  = tid >> 5;
    const int warp_m = wid >> 2;   // 0..1 (64 oc each)
    const int warp_n = wid & 3;    // 0..3 (32 px each)
    const int lrow = lane & 15;
    const int lcol = lane >> 4;

    if (EPI == 0 && z < 2 && tid < 128) rsm[tid] = 0.f;

    float c[4][4][4];
#pragma unroll
    for (int i = 0; i < 4; ++i)
#pragma unroll
        for (int j = 0; j < 4; ++j)
#pragma unroll
            for (int r = 0; r < 4; ++r) c[i][j][r] = 0.f;

    const size_t inb = (size_t)b * PSZ * CCH;

    auto bsid_of = [&](int s) { return (EPI == 1 && s >= 36) ? 12 + (s - 36) : s / 3; };

    auto stage_w = [&](int s) {
        const uint32_t base = sb + (uint32_t)(s % 3) * 16384;
        const char* asrc = (EPI == 1 && s >= 36)
            ? (const char*)wblob2 + (size_t)(z * 4 + (s - 36)) * 16384
            : (const char*)wblob  + (size_t)((z * 4 + s / 9) * 9 + (s % 9)) * 16384;
#pragma unroll
        for (int t = 0; t < 4; ++t) {
            int i = tid + t * 256;
            cpa16(base + i * 16, asrc + i * 16);
        }
    };
    auto stage_b = [&](int bsid) {
        int chunk, dy;
        const __half* src;
        if (EPI == 1 && bsid >= 12) { chunk = bsid - 12; dy = 0; src = inx; }
        else                        { chunk = bsid / 3;  dy = bsid % 3 - 1; src = in; }
        const uint32_t base = sb + 49152 + (uint32_t)(bsid % 3) * 16640;
        const __half* bp = src + inb + (size_t)(h + dy + 1) * PH * CCH + chunk * 64;
        for (int i = tid; i < 1040; i += 256) {       // 130 rows x 8 kc
            int wp = i >> 3;
            int kc = i & 7;
            cpa16(base + wp * 128 + ((kc ^ (wp & 7)) * 16), bp + (size_t)wp * CCH + kc * 8);
        }
    };

    stage_w(0);
    stage_b(0);
    CP_COMMIT();
    int staged_b = 0;

    for (int s = 0; s < NSTEP; ++s) {
        if (s + 1 < NSTEP) {
            stage_w(s + 1);
            int nb = bsid_of(s + 1);
            if (nb != staged_b) { stage_b(nb); staged_b = nb; }
            CP_COMMIT();
            CP_WAIT(1);
        } else {
            CP_WAIT(0);
        }
        __syncthreads();

        const uint32_t Ab = sb + (uint32_t)(s % 3) * 16384;
        const uint32_t Bb = sb + 49152 + (uint32_t)(bsid_of(s) % 3) * 16640;
        const int dxp = (EPI == 1 && s >= 36) ? 1 : (s % 3);   // dx+1

#pragma unroll
        for (int kk = 0; kk < 4; ++kk) {
            const int kc = kk * 2 + lcol;
            uint32_t a[4][4], bbf[4][2];
#pragma unroll
            for (int i = 0; i < 4; ++i) {
                int row = warp_m * 64 + i * 16 + lrow;
                ldsm4(a[i], Ab + (uint32_t)(row * 128 + ((kc ^ (row & 7)) * 16)));
            }
#pragma unroll
            for (int j = 0; j < 2; ++j) {
                int row = warp_n * 32 + j * 16 + lrow + dxp;
                uint32_t q[4];
                ldsm4(q, Bb + (uint32_t)(row * 128 + ((kc ^ (row & 7)) * 16)));
                bbf[j * 2 + 0][0] = q[0]; bbf[j * 2 + 0][1] = q[2];
                bbf[j * 2 + 1][0] = q[1]; bbf[j * 2 + 1][1] = q[3];
            }
#pragma unroll
            for (int i = 0; i < 4; ++i)
#pragma unroll
                for (int j = 0; j < 4; ++j) mma16816(c[i][j], a[i], bbf[j]);
        }
    }

    // ---- epilogue ----
    const int quad = lane >> 2;
    const int tq   = lane & 3;
    const int ocb  = (EPI == 0) ? (z & 1) * 128 : z * 128;
    const bool up  = (EPI == 0) && (z < 2);
    const float* gp = (EPI == 0 && z >= 2) ? gB : gA;
    const float* bp = (EPI == 0 && z >= 2) ? bB : bA;
    const float* mp = (EPI == 0 && z >= 2) ? mB : mA;
    const float* vp = (EPI == 0 && z >= 2) ? vB : vA;

    if (EPI == 1) {
        __syncthreads();   // mainloop SMEM reads complete before bounce reuse
        __half* sbuf = (__half*)smem;   // [w 128][oc 128], row stride 136 halves
#pragma unroll
        for (int i = 0; i < 4; ++i)
#pragma unroll
            for (int h2 = 0; h2 < 2; ++h2) {
                const int ocl = warp_m * 64 + i * 16 + quad + h2 * 8;
                const int oc  = ocb + ocl;
                const float shift = (bA[oc] - mA[oc] * (gA[oc] * rsqrtf(vA[oc] + 1e-5f)))
                                  + (bB[oc] - mB[oc] * (gB[oc] * rsqrtf(vB[oc] + 1e-5f)));
#pragma unroll
                for (int j = 0; j < 4; ++j) {
                    const int w = warp_n * 32 + j * 8 + tq * 2;
                    sbuf[w * 136 + ocl]       = __float2half_rn(fmaxf(c[i][j][h2 * 2 + 0] + shift, 0.f));
                    sbuf[(w + 1) * 136 + ocl] = __float2half_rn(fmaxf(c[i][j][h2 * 2 + 1] + shift, 0.f));
                }
            }
        __syncthreads();
        const int w    = tid >> 1;
        const int half = tid & 1;
        const uint4* srcp = (const uint4*)(sbuf + w * 136 + half * 64);
        uint4* gdst = (uint4*)(outh + ((size_t)b * PSZ + (size_t)(h + 1) * PH + (w + 1)) * CCH
                               + ocb + half * 64);
#pragma unroll
        for (int q = 0; q < 8; ++q) gdst[q] = srcp[q];
        return;
    }

#pragma unroll
    for (int i = 0; i < 4; ++i) {
#pragma unroll
        for (int h2 = 0; h2 < 2; ++h2) {
            const int ocl = warp_m * 64 + i * 16 + quad + h2 * 8;
            const int oc  = ocb + ocl;
            const float sh = bp[oc] - mp[oc] * (gp[oc] * rsqrtf(vp[oc] + 1e-5f));
            if (up) {
                float m = 0.f;
#pragma unroll
                for (int j = 0; j < 4; ++j) {
                    m = fmaxf(m, c[i][j][h2 * 2 + 0] + sh);
                    m = fmaxf(m, c[i][j][h2 * 2 + 1] + sh);
                }
                atomicMax((unsigned*)&rsm[ocl], __float_as_uint(fmaxf(m, 0.f)));
            } else {
                size_t rowbase = ((size_t)b * CCH + oc) * HW + (size_t)h * WWD;
#pragma unroll
                for (int j = 0; j < 4; ++j) {
                    const int w = warp_n * 32 + j * 8 + tq * 2;
                    float v0 = fmaxf(c[i][j][h2 * 2 + 0] + sh, 0.f);
                    float v1 = fmaxf(c[i][j][h2 * 2 + 1] + sh, 0.f);
                    float* dst = (EPI == 0) ? out1 : out0;
                    *(float2*)(dst + rowbase + w) = make_float2(v0, v1);
                }
            }
        }
    }
    if (up) {
        __syncthreads();
        if (tid < 128)
            out0[((size_t)b * HH + h) * CCH + z * 128 + tid] = rsm[tid];
    }
}

// ---------------- weight prepack: fold BN scale; one thread per (img, ocl, icl) ----------------
__global__ void prepack_kernel(const float* __restrict__ srcA, const float* __restrict__ srcB,
                               const float* __restrict__ gSA, const float* __restrict__ vSA,
                               const float* __restrict__ gSB, const float* __restrict__ vSB,
                               int zsplit, int NSH, __half* __restrict__ blob, int total)
{
    int idx = blockIdx.x * 256 + threadIdx.x;
    if (idx >= total) return;
    int icl  = idx & 63;
    int ocl  = (idx >> 6) & 127;
    int rest = idx >> 13;
    int r = rest % NSH; rest /= NSH;
    int chunk = rest & 3;
    int zz    = rest >> 2;
    const float* src = srcA;
    const float* gS = gSA;
    const float* vS = vSA;
    int o = zz * 128 + ocl;
    if (zz >= zsplit) { src = srcB; gS = gSB; vS = vSB; o = (zz - zsplit) * 128 + ocl; }
    int ic = chunk * 64 + icl;
    float sc = gS[o] * rsqrtf(vS[o] + 1e-5f);
    float w = src[(size_t)(o * 256 + ic) * NSH + r] * sc;
    size_t base = (size_t)((zz * 4 + chunk) * NSH + r) * 8192;
    uint32_t off = (uint32_t)(ocl * 64 + (((icl >> 3) ^ (ocl & 7)) * 8) + (icl & 7));
    blob[base + off] = __float2half_rn(w);
}

// ---------------- zero borders of the 3 padded buffers ----------------
__global__ void zero_border_kernel(__half* a, __half* b, __half* c) {
    int idx = blockIdx.x * 256 + threadIdx.x;   // 4*516*256
    int ch   = idx & 255;
    int rest = idx >> 8;
    int p    = rest % 516;
    int bb   = rest / 516;
    int h, w;
    if (p < 260) { h = (p < 130) ? 0 : 129; w = p % 130; }
    else         { int q = p - 260; h = 1 + (q & 127); w = (q >> 7) * 129; }
    size_t i = ((size_t)bb * PSZ + (size_t)h * PH + w) * CCH + ch;
    a[i] = __float2half(0.f); b[i] = __float2half(0.f); c[i] = __float2half(0.f);
}

// ---------------- fp32 NCHW -> padded [h][w][c] fp16 ----------------
__global__ void pad_convert_kernel(const float* __restrict__ src, __half* __restrict__ dst)
{
    __shared__ float s[256][33];
    const int w0 = blockIdx.x * 32;
    const int h  = blockIdx.y;
    const int b  = blockIdx.z;
    const int tid = threadIdx.x;
    const int wl8 = tid & 31;
#pragma unroll 4
    for (int i = 0; i < 32; ++i) {
        int c = i * 8 + (tid >> 5);
        s[c][wl8] = src[((size_t)(b * CCH + c) * HH + h) * WWD + w0 + wl8];
    }
    __syncthreads();
    const int wl = tid >> 3;
    const int cg = (tid & 7) * 32;
    __align__(16) __half v16[32];
#pragma unroll
    for (int j = 0; j < 32; ++j)
        v16[j] = __float2half_rn(s[cg + j][wl]);
    size_t base = ((size_t)b * PSZ + (size_t)(h + 1) * PH + (w0 + wl + 1)) * CCH + cg;
    uint4* dp = (uint4*)(dst + base);
    const uint4* vs = (const uint4*)v16;
#pragma unroll
    for (int q = 0; q < 4; ++q) dp[q] = vs[q];
}

// ---------------- column max over H (NCHW fp32 in) -> [b][w][c] ----------------
__global__ void colmaxT_kernel(const float* __restrict__ in, float* __restrict__ outT) {
    int idx = blockIdx.x * 256 + threadIdx.x;   // (b*256+oc)*128 + w
    int w  = idx & 127;
    int bc = idx >> 7;
    int oc = bc & 255;
    int b  = bc >> 8;
    const float* p = in + (size_t)bc * HW + w;
    float m = -FLT_MAX;
#pragma unroll 4
    for (int h = 0; h < HH; ++h) m = fmaxf(m, p[(size_t)h * WWD]);
    outT[((size_t)b * WWD + w) * CCH + oc] = m;
}

// ---------------- S = rmax + cmax -> padded fp16 ----------------
__global__ void sbuild_kernel(const float* __restrict__ rT, const float* __restrict__ cT,
                              __half* __restrict__ dst)
{
    const int w = blockIdx.x, h = blockIdx.y, b = blockIdx.z;
    const int c = threadIdx.x;
    float v = rT[((size_t)b * HH + h) * CCH + c] + cT[((size_t)b * WWD + w) * CCH + c];
    dst[((size_t)b * PSZ + (size_t)(h + 1) * PH + (w + 1)) * CCH + c] = __float2half_rn(v);
}

// ---------------- launch ----------------
extern "C" void kernel_launch(void* const* d_in, const int* in_sizes, int n_in,
                              void* d_out, int out_size) {
    (void)in_sizes; (void)n_in; (void)out_size;
    const float* x      = (const float*)d_in[0];
    const float* w_up   = (const float*)d_in[1];
    const float* g_up   = (const float*)d_in[2];
    const float* b_up   = (const float*)d_in[3];
    const float* m_up   = (const float*)d_in[4];
    const float* v_up   = (const float*)d_in[5];
    const float* w_down = (const float*)d_in[6];
    const float* g_down = (const float*)d_in[7];
    const float* b_down = (const float*)d_in[8];
    const float* m_down = (const float*)d_in[9];
    const float* v_down = (const float*)d_in[10];
    const float* w_p    = (const float*)d_in[11];
    const float* g_p    = (const float*)d_in[12];
    const float* b_p    = (const float*)d_in[13];
    const float* m_p    = (const float*)d_in[14];
    const float* v_p    = (const float*)d_in[15];
    const float* w_c1   = (const float*)d_in[16];
    const float* g_c1   = (const float*)d_in[17];
    const float* b_c1   = (const float*)d_in[18];
    const float* m_c1   = (const float*)d_in[19];
    const float* v_c1   = (const float*)d_in[20];
    const float* w_c2   = (const float*)d_in[21];
    const float* g_c2   = (const float*)d_in[22];
    const float* b_c2   = (const float*)d_in[23];
    const float* m_c2   = (const float*)d_in[24];
    const float* v_c2   = (const float*)d_in[25];
    float* out = (float*)d_out;

    float *bufA, *rmaxT, *cmaxT;
    __half *px, *pt, *pt2, *bl1, *blP, *blC2, *blC1;
    cudaGetSymbolAddress((void**)&bufA,  g_bufA);
    cudaGetSymbolAddress((void**)&rmaxT, g_rmaxT);
    cudaGetSymbolAddress((void**)&cmaxT, g_cmaxT);
    cudaGetSymbolAddress((void**)&px,    g_px);
    cudaGetSymbolAddress((void**)&pt,    g_pt);
    cudaGetSymbolAddress((void**)&pt2,   g_pt2);
    cudaGetSymbolAddress((void**)&bl1,   g_blob1);
    cudaGetSymbolAddress((void**)&blP,   g_blobP);
    cudaGetSymbolAddress((void**)&blC2,  g_blobC2);
    cudaGetSymbolAddress((void**)&blC1,  g_blobC1);

    cudaFuncSetAttribute(conv_mma<0>, cudaFuncAttributeMaxDynamicSharedMemorySize, CONV_SMEM);
    cudaFuncSetAttribute(conv_mma<1>, cudaFuncAttributeMaxDynamicSharedMemorySize, CONV_SMEM);
    cudaFuncSetAttribute(conv_mma<2>, cudaFuncAttributeMaxDynamicSharedMemorySize, CONV_SMEM);

    // totals = images * 8192 (BN scale folded)
    prepack_kernel<<<1179648/256, 256>>>(w_up, w_down, g_up, v_up, g_down, v_down, 2, 9, bl1, 1179648);
    prepack_kernel<<<589824/256,  256>>>(w_p,  w_p,  g_p,  v_p,  g_p,  v_p,  2, 9, blP,  589824);
    prepack_kernel<<<589824/256,  256>>>(w_c2, w_c2, g_c2, v_c2, g_c2, v_c2, 2, 9, blC2, 589824);
    prepack_kernel<<<65536/256,   256>>>(w_c1, w_c1, g_c1, v_c1, g_c1, v_c1, 2, 1, blC1, 65536);
    zero_border_kernel<<<(4*516*256)/256, 256>>>(px, pt, pt2);
    pad_convert_kernel<<<dim3(4,128,4), 256>>>(x, px);

    // fused up+down: z0,1 -> rowmaxT; z2,3 -> down relu map in bufA
    conv_mma<0><<<dim3(HH,BBATCH,4), 256, CONV_SMEM>>>(px, px, bl1, bl1,
        g_up, b_up, m_up, v_up, g_down, b_down, m_down, v_down,
        rmaxT, bufA, nullptr);
    colmaxT_kernel<<<512, 256>>>(bufA, cmaxT);
    sbuild_kernel<<<dim3(128,128,4), 256>>>(rmaxT, cmaxT, pt);

    // relu1 = relu(conv_p(S)·sc_p + conv_c1(x)·sc_c1 + sh_p + sh_c1) -> pt2 (fp16 padded)
    conv_mma<1><<<dim3(HH,BBATCH,2), 256, CONV_SMEM>>>(pt, px, blP, blC1,
        g_p, b_p, m_p, v_p, g_c1, b_c1, m_c1, v_c1,
        nullptr, nullptr, pt2);

    // out = relu(conv_c2(relu1)·sc_c2 + sh_c2)
    conv_mma<2><<<dim3(HH,BBATCH,2), 256, CONV_SMEM>>>(pt2, pt2, blC2, blC2,
        g_c2, b_c2, m_c2, v_c2, g_c2, b_c2, m_c2, v_c2,
        out, nullptr, nullptr);
}

// round 14
// speedup vs baseline: 8.5931x; 1.0217x over previous
#include <cuda_runtime.h>
#include <cuda_fp16.h>
#include <math.h>
#include <float.h>
#include <stdint.h>

#define BBATCH 4
#define CCH 256
#define HH 128
#define WWD 128
#define HW (HH*WWD)
#define CHW (CCH*HW)
#define TOTN (BBATCH*CHW)
#define PH 130
#define PSZ (PH*PH)
#define PADTOT (BBATCH*PSZ*CCH)

// ---------------- device scratch ----------------
__device__ __align__(256) __half g_px[PADTOT];            // padded x
__device__ __align__(256) __half g_pt[PADTOT];            // padded S
__device__ __align__(256) __half g_pt2[PADTOT];           // padded relu1
__device__ __align__(256) float g_rmaxT[BBATCH*HH*CCH];   // [b][h][c]
__device__ __align__(256) float g_cmaxT[BBATCH*WWD*CCH];  // [b][w][c]
__device__ __align__(256) __half g_blob1[4*4*9*8192];
__device__ __align__(256) __half g_blobP[2*4*9*8192];
__device__ __align__(256) __half g_blobC2[2*4*9*8192];
__device__ __align__(256) __half g_blobC1[2*4*8192];

// ---------------- PTX helpers (plain sm_100 legal) ----------------
__device__ __forceinline__ uint32_t cvta_smem(const void* p) {
    uint32_t a;
    asm("{ .reg .u64 t; cvta.to.shared.u64 t, %1; cvt.u32.u64 %0, t; }" : "=r"(a) : "l"(p));
    return a;
}
__device__ __forceinline__ void cpa16(uint32_t s, const void* g) {
    asm volatile("{ .reg .u64 ga; cvta.to.global.u64 ga, %1; cp.async.cg.shared.global [%0], [ga], 16; }"
        :: "r"(s), "l"(g) : "memory");
}
#define CP_COMMIT() asm volatile("cp.async.commit_group;" ::: "memory")
#define CP_WAIT(n)  asm volatile("cp.async.wait_group %0;" :: "n"(n) : "memory")

__device__ __forceinline__ void ldsm4(uint32_t* r, uint32_t addr) {
    asm volatile("ldmatrix.sync.aligned.m8n8.x4.shared.b16 {%0,%1,%2,%3}, [%4];"
        : "=r"(r[0]), "=r"(r[1]), "=r"(r[2]), "=r"(r[3]) : "r"(addr));
}
__device__ __forceinline__ void mma16816(float* c, const uint32_t* a, const uint32_t* b) {
    asm volatile("mma.sync.aligned.m16n8k16.row.col.f32.f16.f16.f32 "
        "{%0,%1,%2,%3}, {%4,%5,%6,%7}, {%8,%9}, {%0,%1,%2,%3};"
        : "+f"(c[0]), "+f"(c[1]), "+f"(c[2]), "+f"(c[3])
        : "r"(a[0]), "r"(a[1]), "r"(a[2]), "r"(a[3]), "r"(b[0]), "r"(b[1]));
}

// ---------------- mma.sync fp16 conv (BN scale folded into weights) ----------------
// SMEM: W ring 3x16K @0 | B ring 3x16640 @49152 | rsm @99072. Total 99584 -> 2 CTAs/SM.
// EPI 0: fused up+down (z0,1 up -> rowmax to out0[b][h][c];
//        z2,3 down -> ATOMIC colmax into out1[b][w][c], no map materialized)
// EPI 1: conv_p(S) + conv_c1(x) fused (36+4 steps); relu -> fp16 padded outh
// EPI 2: conv_c2: relu -> out0 fp32 (d_out)
#define CONV_SMEM 99584
template<int EPI>
__global__ __launch_bounds__(256, 2) void conv_mma(
    const __half* __restrict__ in, const __half* __restrict__ inx,
    const __half* __restrict__ wblob, const __half* __restrict__ wblob2,
    const float* __restrict__ gA, const float* __restrict__ bA,
    const float* __restrict__ mA, const float* __restrict__ vA,
    const float* __restrict__ gB, const float* __restrict__ bB,
    const float* __restrict__ mB, const float* __restrict__ vB,
    float* __restrict__ out0, float* __restrict__ out1, __half* __restrict__ outh)
{
    constexpr int NSTEP = (EPI == 1) ? 40 : 36;
    extern __shared__ char smem[];
    const uint32_t sb = cvta_smem(smem);
    float* rsm = (float*)(smem + 99072);

    const int tid  = threadIdx.x;
    const int h    = blockIdx.x;
    const int b    = blockIdx.y;
    const int z    = blockIdx.z;
    const int lane = tid & 31;
    const int wid  = tid >> 5;
    const int warp_m = wid >> 2;   // 0..1 (64 oc each)
    const int warp_n = wid & 3;    // 0..3 (32 px each)
    const int lrow = lane & 15;
    const int lcol = lane >> 4;

    if (EPI == 0 && z < 2 && tid < 128) rsm[tid] = 0.f;

    float c[4][4][4];
#pragma unroll
    for (int i = 0; i < 4; ++i)
#pragma unroll
        for (int j = 0; j < 4; ++j)
#pragma unroll
            for (int r = 0; r < 4; ++r) c[i][j][r] = 0.f;

    const size_t inb = (size_t)b * PSZ * CCH;

    auto bsid_of = [&](int s) { return (EPI == 1 && s >= 36) ? 12 + (s - 36) : s / 3; };

    auto stage_w = [&](int s) {
        const uint32_t base = sb + (uint32_t)(s % 3) * 16384;
        const char* asrc = (EPI == 1 && s >= 36)
            ? (const char*)wblob2 + (size_t)(z * 4 + (s - 36)) * 16384
            : (const char*)wblob  + (size_t)((z * 4 + s / 9) * 9 + (s % 9)) * 16384;
#pragma unroll
        for (int t = 0; t < 4; ++t) {
            int i = tid + t * 256;
            cpa16(base + i * 16, asrc + i * 16);
        }
    };
    auto stage_b = [&](int bsid) {
        int chunk, dy;
        const __half* src;
        if (EPI == 1 && bsid >= 12) { chunk = bsid - 12; dy = 0; src = inx; }
        else                        { chunk = bsid / 3;  dy = bsid % 3 - 1; src = in; }
        const uint32_t base = sb + 49152 + (uint32_t)(bsid % 3) * 16640;
        const __half* bp = src + inb + (size_t)(h + dy + 1) * PH * CCH + chunk * 64;
        for (int i = tid; i < 1040; i += 256) {       // 130 rows x 8 kc
            int wp = i >> 3;
            int kc = i & 7;
            cpa16(base + wp * 128 + ((kc ^ (wp & 7)) * 16), bp + (size_t)wp * CCH + kc * 8);
        }
    };

    stage_w(0);
    stage_b(0);
    CP_COMMIT();
    int staged_b = 0;

    for (int s = 0; s < NSTEP; ++s) {
        if (s + 1 < NSTEP) {
            stage_w(s + 1);
            int nb = bsid_of(s + 1);
            if (nb != staged_b) { stage_b(nb); staged_b = nb; }
            CP_COMMIT();
            CP_WAIT(1);
        } else {
            CP_WAIT(0);
        }
        __syncthreads();

        const uint32_t Ab = sb + (uint32_t)(s % 3) * 16384;
        const uint32_t Bb = sb + 49152 + (uint32_t)(bsid_of(s) % 3) * 16640;
        const int dxp = (EPI == 1 && s >= 36) ? 1 : (s % 3);   // dx+1

#pragma unroll
        for (int kk = 0; kk < 4; ++kk) {
            const int kc = kk * 2 + lcol;
            uint32_t a[4][4], bbf[4][2];
#pragma unroll
            for (int i = 0; i < 4; ++i) {
                int row = warp_m * 64 + i * 16 + lrow;
                ldsm4(a[i], Ab + (uint32_t)(row * 128 + ((kc ^ (row & 7)) * 16)));
            }
#pragma unroll
            for (int j = 0; j < 2; ++j) {
                int row = warp_n * 32 + j * 16 + lrow + dxp;
                uint32_t q[4];
                ldsm4(q, Bb + (uint32_t)(row * 128 + ((kc ^ (row & 7)) * 16)));
                bbf[j * 2 + 0][0] = q[0]; bbf[j * 2 + 0][1] = q[2];
                bbf[j * 2 + 1][0] = q[1]; bbf[j * 2 + 1][1] = q[3];
            }
#pragma unroll
            for (int i = 0; i < 4; ++i)
#pragma unroll
                for (int j = 0; j < 4; ++j) mma16816(c[i][j], a[i], bbf[j]);
        }
    }

    // ---- epilogue ----
    const int quad = lane >> 2;
    const int tq   = lane & 3;
    const int ocb  = (EPI == 0) ? (z & 1) * 128 : z * 128;
    const bool up  = (EPI == 0) && (z < 2);
    const float* gp = (EPI == 0 && z >= 2) ? gB : gA;
    const float* bp = (EPI == 0 && z >= 2) ? bB : bA;
    const float* mp = (EPI == 0 && z >= 2) ? mB : mA;
    const float* vp = (EPI == 0 && z >= 2) ? vB : vA;

    if (EPI == 1) {
        __syncthreads();   // mainloop SMEM reads complete before bounce reuse
        __half* sbuf = (__half*)smem;   // [w 128][oc 128], row stride 136 halves
#pragma unroll
        for (int i = 0; i < 4; ++i)
#pragma unroll
            for (int h2 = 0; h2 < 2; ++h2) {
                const int ocl = warp_m * 64 + i * 16 + quad + h2 * 8;
                const int oc  = ocb + ocl;
                const float shift = (bA[oc] - mA[oc] * (gA[oc] * rsqrtf(vA[oc] + 1e-5f)))
                                  + (bB[oc] - mB[oc] * (gB[oc] * rsqrtf(vB[oc] + 1e-5f)));
#pragma unroll
                for (int j = 0; j < 4; ++j) {
                    const int w = warp_n * 32 + j * 8 + tq * 2;
                    sbuf[w * 136 + ocl]       = __float2half_rn(fmaxf(c[i][j][h2 * 2 + 0] + shift, 0.f));
                    sbuf[(w + 1) * 136 + ocl] = __float2half_rn(fmaxf(c[i][j][h2 * 2 + 1] + shift, 0.f));
                }
            }
        __syncthreads();
        const int w    = tid >> 1;
        const int half = tid & 1;
        const uint4* srcp = (const uint4*)(sbuf + w * 136 + half * 64);
        uint4* gdst = (uint4*)(outh + ((size_t)b * PSZ + (size_t)(h + 1) * PH + (w + 1)) * CCH
                               + ocb + half * 64);
#pragma unroll
        for (int q = 0; q < 8; ++q) gdst[q] = srcp[q];
        return;
    }

#pragma unroll
    for (int i = 0; i < 4; ++i) {
#pragma unroll
        for (int h2 = 0; h2 < 2; ++h2) {
            const int ocl = warp_m * 64 + i * 16 + quad + h2 * 8;
            const int oc  = ocb + ocl;
            const float sh = bp[oc] - mp[oc] * (gp[oc] * rsqrtf(vp[oc] + 1e-5f));
            if (up) {
                float m = 0.f;
#pragma unroll
                for (int j = 0; j < 4; ++j) {
                    m = fmaxf(m, c[i][j][h2 * 2 + 0] + sh);
                    m = fmaxf(m, c[i][j][h2 * 2 + 1] + sh);
                }
                atomicMax((unsigned*)&rsm[ocl], __float_as_uint(fmaxf(m, 0.f)));
            } else if (EPI == 0) {
                // down: fused column-max (relu'd values >= 0 -> uint order == float order)
                float* cm = out1 + ((size_t)b * WWD) * CCH;
#pragma unroll
                for (int j = 0; j < 4; ++j) {
                    const int w = warp_n * 32 + j * 8 + tq * 2;
                    float v0 = fmaxf(c[i][j][h2 * 2 + 0] + sh, 0.f);
                    float v1 = fmaxf(c[i][j][h2 * 2 + 1] + sh, 0.f);
                    atomicMax((unsigned*)&cm[(size_t)w * CCH + oc],       __float_as_uint(v0));
                    atomicMax((unsigned*)&cm[(size_t)(w + 1) * CCH + oc], __float_as_uint(v1));
                }
            } else {  // EPI == 2: final output, NCHW fp32
                size_t rowbase = ((size_t)b * CCH + oc) * HW + (size_t)h * WWD;
#pragma unroll
                for (int j = 0; j < 4; ++j) {
                    const int w = warp_n * 32 + j * 8 + tq * 2;
                    float v0 = fmaxf(c[i][j][h2 * 2 + 0] + sh, 0.f);
                    float v1 = fmaxf(c[i][j][h2 * 2 + 1] + sh, 0.f);
                    *(float2*)(out0 + rowbase + w) = make_float2(v0, v1);
                }
            }
        }
    }
    if (up) {
        __syncthreads();
        if (tid < 128)
            out0[((size_t)b * HH + h) * CCH + z * 128 + tid] = rsm[tid];
    }
}

// ---------------- weight prepack: fold BN scale; one thread per (img, ocl, icl) ----------------
__global__ void prepack_kernel(const float* __restrict__ srcA, const float* __restrict__ srcB,
                               const float* __restrict__ gSA, const float* __restrict__ vSA,
                               const float* __restrict__ gSB, const float* __restrict__ vSB,
                               int zsplit, int NSH, __half* __restrict__ blob, int total)
{
    int idx = blockIdx.x * 256 + threadIdx.x;
    if (idx >= total) return;
    int icl  = idx & 63;
    int ocl  = (idx >> 6) & 127;
    int rest = idx >> 13;
    int r = rest % NSH; rest /= NSH;
    int chunk = rest & 3;
    int zz    = rest >> 2;
    const float* src = srcA;
    const float* gS = gSA;
    const float* vS = vSA;
    int o = zz * 128 + ocl;
    if (zz >= zsplit) { src = srcB; gS = gSB; vS = vSB; o = (zz - zsplit) * 128 + ocl; }
    int ic = chunk * 64 + icl;
    float sc = gS[o] * rsqrtf(vS[o] + 1e-5f);
    float w = src[(size_t)(o * 256 + ic) * NSH + r] * sc;
    size_t base = (size_t)((zz * 4 + chunk) * NSH + r) * 8192;
    uint32_t off = (uint32_t)(ocl * 64 + (((icl >> 3) ^ (ocl & 7)) * 8) + (icl & 7));
    blob[base + off] = __float2half_rn(w);
}

// ---------------- zero borders of padded buffers + zero cmax accumulator ----------------
// idx < 4*516*256: border zeroing. idx >= that: cmaxT zeroing (4*128*256 floats).
__global__ void zero_border_kernel(__half* a, __half* b, __half* c, float* cmax) {
    int idx = blockIdx.x * 256 + threadIdx.x;
    const int NB = 4 * 516 * 256;
    if (idx < NB) {
        int ch   = idx & 255;
        int rest = idx >> 8;
        int p    = rest % 516;
        int bb   = rest / 516;
        int h, w;
        if (p < 260) { h = (p < 130) ? 0 : 129; w = p % 130; }
        else         { int q = p - 260; h = 1 + (q & 127); w = (q >> 7) * 129; }
        size_t i = ((size_t)bb * PSZ + (size_t)h * PH + w) * CCH + ch;
        a[i] = __float2half(0.f); b[i] = __float2half(0.f); c[i] = __float2half(0.f);
    } else {
        int j = idx - NB;
        if (j < BBATCH * WWD * CCH) cmax[j] = 0.f;
    }
}

// ---------------- fp32 NCHW -> padded [h][w][c] fp16 ----------------
__global__ void pad_convert_kernel(const float* __restrict__ src, __half* __restrict__ dst)
{
    __shared__ float s[256][33];
    const int w0 = blockIdx.x * 32;
    const int h  = blockIdx.y;
    const int b  = blockIdx.z;
    const int tid = threadIdx.x;
    const int wl8 = tid & 31;
#pragma unroll 4
    for (int i = 0; i < 32; ++i) {
        int c = i * 8 + (tid >> 5);
        s[c][wl8] = src[((size_t)(b * CCH + c) * HH + h) * WWD + w0 + wl8];
    }
    __syncthreads();
    const int wl = tid >> 3;
    const int cg = (tid & 7) * 32;
    __align__(16) __half v16[32];
#pragma unroll
    for (int j = 0; j < 32; ++j)
        v16[j] = __float2half_rn(s[cg + j][wl]);
    size_t base = ((size_t)b * PSZ + (size_t)(h + 1) * PH + (w0 + wl + 1)) * CCH + cg;
    uint4* dp = (uint4*)(dst + base);
    const uint4* vs = (const uint4*)v16;
#pragma unroll
    for (int q = 0; q < 4; ++q) dp[q] = vs[q];
}

// ---------------- S = rmax + cmax -> padded fp16 ----------------
__global__ void sbuild_kernel(const float* __restrict__ rT, const float* __restrict__ cT,
                              __half* __restrict__ dst)
{
    const int w = blockIdx.x, h = blockIdx.y, b = blockIdx.z;
    const int c = threadIdx.x;
    float v = rT[((size_t)b * HH + h) * CCH + c] + cT[((size_t)b * WWD + w) * CCH + c];
    dst[((size_t)b * PSZ + (size_t)(h + 1) * PH + (w + 1)) * CCH + c] = __float2half_rn(v);
}

// ---------------- launch ----------------
extern "C" void kernel_launch(void* const* d_in, const int* in_sizes, int n_in,
                              void* d_out, int out_size) {
    (void)in_sizes; (void)n_in; (void)out_size;
    const float* x      = (const float*)d_in[0];
    const float* w_up   = (const float*)d_in[1];
    const float* g_up   = (const float*)d_in[2];
    const float* b_up   = (const float*)d_in[3];
    const float* m_up   = (const float*)d_in[4];
    const float* v_up   = (const float*)d_in[5];
    const float* w_down = (const float*)d_in[6];
    const float* g_down = (const float*)d_in[7];
    const float* b_down = (const float*)d_in[8];
    const float* m_down = (const float*)d_in[9];
    const float* v_down = (const float*)d_in[10];
    const float* w_p    = (const float*)d_in[11];
    const float* g_p    = (const float*)d_in[12];
    const float* b_p    = (const float*)d_in[13];
    const float* m_p    = (const float*)d_in[14];
    const float* v_p    = (const float*)d_in[15];
    const float* w_c1   = (const float*)d_in[16];
    const float* g_c1   = (const float*)d_in[17];
    const float* b_c1   = (const float*)d_in[18];
    const float* m_c1   = (const float*)d_in[19];
    const float* v_c1   = (const float*)d_in[20];
    const float* w_c2   = (const float*)d_in[21];
    const float* g_c2   = (const float*)d_in[22];
    const float* b_c2   = (const float*)d_in[23];
    const float* m_c2   = (const float*)d_in[24];
    const float* v_c2   = (const float*)d_in[25];
    float* out = (float*)d_out;

    float *rmaxT, *cmaxT;
    __half *px, *pt, *pt2, *bl1, *blP, *blC2, *blC1;
    cudaGetSymbolAddress((void**)&rmaxT, g_rmaxT);
    cudaGetSymbolAddress((void**)&cmaxT, g_cmaxT);
    cudaGetSymbolAddress((void**)&px,    g_px);
    cudaGetSymbolAddress((void**)&pt,    g_pt);
    cudaGetSymbolAddress((void**)&pt2,   g_pt2);
    cudaGetSymbolAddress((void**)&bl1,   g_blob1);
    cudaGetSymbolAddress((void**)&blP,   g_blobP);
    cudaGetSymbolAddress((void**)&blC2,  g_blobC2);
    cudaGetSymbolAddress((void**)&blC1,  g_blobC1);

    cudaFuncSetAttribute(conv_mma<0>, cudaFuncAttributeMaxDynamicSharedMemorySize, CONV_SMEM);
    cudaFuncSetAttribute(conv_mma<1>, cudaFuncAttributeMaxDynamicSharedMemorySize, CONV_SMEM);
    cudaFuncSetAttribute(conv_mma<2>, cudaFuncAttributeMaxDynamicSharedMemorySize, CONV_SMEM);

    // totals = images * 8192 (BN scale folded)
    prepack_kernel<<<1179648/256, 256>>>(w_up, w_down, g_up, v_up, g_down, v_down, 2, 9, bl1, 1179648);
    prepack_kernel<<<589824/256,  256>>>(w_p,  w_p,  g_p,  v_p,  g_p,  v_p,  2, 9, blP,  589824);
    prepack_kernel<<<589824/256,  256>>>(w_c2, w_c2, g_c2, v_c2, g_c2, v_c2, 2, 9, blC2, 589824);
    prepack_kernel<<<65536/256,   256>>>(w_c1, w_c1, g_c1, v_c1, g_c1, v_c1, 2, 1, blC1, 65536);
    // borders + cmax zero: 4*516*256 + 4*128*256 = 659456 threads
    zero_border_kernel<<<(4*516*256 + 4*128*256)/256, 256>>>(px, pt, pt2, cmaxT);
    pad_convert_kernel<<<dim3(4,128,4), 256>>>(x, px);

    // fused up+down: z0,1 -> rmaxT; z2,3 -> atomic colmax into cmaxT (no map)
    conv_mma<0><<<dim3(HH,BBATCH,4), 256, CONV_SMEM>>>(px, px, bl1, bl1,
        g_up, b_up, m_up, v_up, g_down, b_down, m_down, v_down,
        rmaxT, cmaxT, nullptr);
    sbuild_kernel<<<dim3(128,128,4), 256>>>(rmaxT, cmaxT, pt);

    // relu1 = relu(conv_p(S) + conv_c1(x) + shifts) -> pt2 (fp16 padded)
    conv_mma<1><<<dim3(HH,BBATCH,2), 256, CONV_SMEM>>>(pt, px, blP, blC1,
        g_p, b_p, m_p, v_p, g_c1, b_c1, m_c1, v_c1,
        nullptr, nullptr, pt2);

    // out = relu(conv_c2(relu1) + sh_c2)
    conv_mma<2><<<dim3(HH,BBATCH,2), 256, CONV_SMEM>>>(pt2, pt2, blC2, blC2,
        g_c2, b_c2, m_c2, v_c2, g_c2, b_c2, m_c2, v_c2,
        out, nullptr, nullptr);
}

// round 16
// speedup vs baseline: 10.7508x; 1.2511x over previous
#include <cuda_runtime.h>
#include <cuda_fp16.h>
#include <math.h>
#include <float.h>
#include <stdint.h>

#define BBATCH 4
#define CCH 256
#define HH 128
#define WWD 128
#define HW (HH*WWD)
#define PH 130
#define PSZ (PH*PH)
#define PADTOT (BBATCH*PSZ*CCH)

// ---------------- device scratch ----------------
__device__ __align__(256) __half g_px[PADTOT];            // padded x
__device__ __align__(256) __half g_pt2[PADTOT];           // padded relu1
__device__ __align__(256) float g_rmaxT[BBATCH*HH*CCH];   // [b][h][c]
__device__ __align__(256) float g_cmaxT[BBATCH*WWD*CCH];  // [b][w][c]
__device__ __align__(256) __half g_blob1[4*4*9*8192];
__device__ __align__(256) __half g_blobC2[2*4*9*8192];
__device__ __align__(256) __half g_blobC1[2*4*8192];
__device__ __align__(256) __half g_blR[3*2*12*8192];      // row-summed conv_p weights
__device__ __align__(256) __half g_blC[3*2*12*8192];      // col-summed conv_p weights
__device__ __align__(256) __half g_R[BBATCH*128*768];     // R[b][h][dy*256+ic]
__device__ __align__(256) __half g_C[BBATCH*128*768];     // C[b][w][dx*256+ic]
__device__ __align__(256) float g_Arow[BBATCH*3*CCH*128]; // A[b][case][oc][h]
__device__ __align__(256) float g_Bcol[BBATCH*3*CCH*128]; // B[b][case][oc][w]

// ---------------- PTX helpers (plain sm_100 legal) ----------------
__device__ __forceinline__ uint32_t cvta_smem(const void* p) {
    uint32_t a;
    asm("{ .reg .u64 t; cvta.to.shared.u64 t, %1; cvt.u32.u64 %0, t; }" : "=r"(a) : "l"(p));
    return a;
}
__device__ __forceinline__ void cpa16(uint32_t s, const void* g) {
    asm volatile("{ .reg .u64 ga; cvta.to.global.u64 ga, %1; cp.async.cg.shared.global [%0], [ga], 16; }"
        :: "r"(s), "l"(g) : "memory");
}
#define CP_COMMIT() asm volatile("cp.async.commit_group;" ::: "memory")
#define CP_WAIT(n)  asm volatile("cp.async.wait_group %0;" :: "n"(n) : "memory")

__device__ __forceinline__ void ldsm4(uint32_t* r, uint32_t addr) {
    asm volatile("ldmatrix.sync.aligned.m8n8.x4.shared.b16 {%0,%1,%2,%3}, [%4];"
        : "=r"(r[0]), "=r"(r[1]), "=r"(r[2]), "=r"(r[3]) : "r"(addr));
}
__device__ __forceinline__ void mma16816(float* c, const uint32_t* a, const uint32_t* b) {
    asm volatile("mma.sync.aligned.m16n8k16.row.col.f32.f16.f16.f32 "
        "{%0,%1,%2,%3}, {%4,%5,%6,%7}, {%8,%9}, {%0,%1,%2,%3};"
        : "+f"(c[0]), "+f"(c[1]), "+f"(c[2]), "+f"(c[3])
        : "r"(a[0]), "r"(a[1]), "r"(a[2]), "r"(a[3]), "r"(b[0]), "r"(b[1]));
}

// ---------------- mma.sync fp16 conv (BN scale folded into weights) ----------------
// EPI 0: fused up+down, 36 steps (z0,1 up -> rowmax; z2,3 down -> atomic colmax)
// EPI 1: conv_c1(x) only, 4 steps; epilogue adds rank-1 conv_p terms A/B + shifts, relu -> fp16 outh
// EPI 2: conv_c2, 36 steps: relu -> out0 fp32 (d_out)
#define CONV_SMEM 99584
template<int EPI>
__global__ __launch_bounds__(256, 2) void conv_mma(
    const __half* __restrict__ in, const __half* __restrict__ wblob,
    const float* __restrict__ gA, const float* __restrict__ bA,
    const float* __restrict__ mA, const float* __restrict__ vA,
    const float* __restrict__ gB, const float* __restrict__ bB,
    const float* __restrict__ mB, const float* __restrict__ vB,
    float* __restrict__ out0, float* __restrict__ out1, __half* __restrict__ outh,
    const float* __restrict__ arow, const float* __restrict__ bcol)
{
    constexpr int NSTEP = (EPI == 1) ? 4 : 36;
    extern __shared__ char smem[];
    const uint32_t sb = cvta_smem(smem);
    float* rsm = (float*)(smem + 99072);

    const int tid  = threadIdx.x;
    const int h    = blockIdx.x;
    const int b    = blockIdx.y;
    const int z    = blockIdx.z;
    const int lane = tid & 31;
    const int wid  = tid >> 5;
    const int warp_m = wid >> 2;
    const int warp_n = wid & 3;
    const int lrow = lane & 15;
    const int lcol = lane >> 4;

    if (EPI == 0 && z < 2 && tid < 128) rsm[tid] = 0.f;

    float c[4][4][4];
#pragma unroll
    for (int i = 0; i < 4; ++i)
#pragma unroll
        for (int j = 0; j < 4; ++j)
#pragma unroll
            for (int r = 0; r < 4; ++r) c[i][j][r] = 0.f;

    const size_t inb = (size_t)b * PSZ * CCH;

    auto bsid_of = [&](int s) { return (EPI == 1) ? s : s / 3; };

    auto stage_w = [&](int s) {
        const uint32_t base = sb + (uint32_t)(s % 3) * 16384;
        const char* asrc = (EPI == 1)
            ? (const char*)wblob + (size_t)(z * 4 + s) * 16384
            : (const char*)wblob + (size_t)((z * 4 + s / 9) * 9 + (s % 9)) * 16384;
#pragma unroll
        for (int t = 0; t < 4; ++t) {
            int i = tid + t * 256;
            cpa16(base + i * 16, asrc + i * 16);
        }
    };
    auto stage_b = [&](int bsid) {
        const int chunk = (EPI == 1) ? bsid : bsid / 3;
        const int dy    = (EPI == 1) ? 0    : bsid % 3 - 1;
        const uint32_t base = sb + 49152 + (uint32_t)(bsid % 3) * 16640;
        const __half* bp = in + inb + (size_t)(h + dy + 1) * PH * CCH + chunk * 64;
        for (int i = tid; i < 1040; i += 256) {
            int wp = i >> 3;
            int kc = i & 7;
            cpa16(base + wp * 128 + ((kc ^ (wp & 7)) * 16), bp + (size_t)wp * CCH + kc * 8);
        }
    };

    stage_w(0);
    stage_b(0);
    CP_COMMIT();
    int staged_b = 0;

    for (int s = 0; s < NSTEP; ++s) {
        if (s + 1 < NSTEP) {
            stage_w(s + 1);
            int nb = bsid_of(s + 1);
            if (nb != staged_b) { stage_b(nb); staged_b = nb; }
            CP_COMMIT();
            CP_WAIT(1);
        } else {
            CP_WAIT(0);
        }
        __syncthreads();

        const uint32_t Ab = sb + (uint32_t)(s % 3) * 16384;
        const uint32_t Bb = sb + 49152 + (uint32_t)(bsid_of(s) % 3) * 16640;
        const int dxp = (EPI == 1) ? 1 : (s % 3);

#pragma unroll
        for (int kk = 0; kk < 4; ++kk) {
            const int kc = kk * 2 + lcol;
            uint32_t a[4][4], bbf[4][2];
#pragma unroll
            for (int i = 0; i < 4; ++i) {
                int row = warp_m * 64 + i * 16 + lrow;
                ldsm4(a[i], Ab + (uint32_t)(row * 128 + ((kc ^ (row & 7)) * 16)));
            }
#pragma unroll
            for (int j = 0; j < 2; ++j) {
                int row = warp_n * 32 + j * 16 + lrow + dxp;
                uint32_t q[4];
                ldsm4(q, Bb + (uint32_t)(row * 128 + ((kc ^ (row & 7)) * 16)));
                bbf[j * 2 + 0][0] = q[0]; bbf[j * 2 + 0][1] = q[2];
                bbf[j * 2 + 1][0] = q[1]; bbf[j * 2 + 1][1] = q[3];
            }
#pragma unroll
            for (int i = 0; i < 4; ++i)
#pragma unroll
                for (int j = 0; j < 4; ++j) mma16816(c[i][j], a[i], bbf[j]);
        }
    }

    // ---- epilogue ----
    const int quad = lane >> 2;
    const int tq   = lane & 3;
    const int ocb  = (EPI == 0) ? (z & 1) * 128 : z * 128;
    const bool up  = (EPI == 0) && (z < 2);
    const float* gp = (EPI == 0 && z >= 2) ? gB : gA;
    const float* bp = (EPI == 0 && z >= 2) ? bB : bA;
    const float* mp = (EPI == 0 && z >= 2) ? mB : mA;
    const float* vp = (EPI == 0 && z >= 2) ? vB : vA;

    if (EPI == 1) {
        __syncthreads();
        __half* sbuf = (__half*)smem;   // [w 128][oc 128], stride 136 halves
        const int chh = (h == 0) ? 0 : (h == 127) ? 2 : 1;
#pragma unroll
        for (int i = 0; i < 4; ++i)
#pragma unroll
            for (int h2 = 0; h2 < 2; ++h2) {
                const int ocl = warp_m * 64 + i * 16 + quad + h2 * 8;
                const int oc  = ocb + ocl;
                const float shift = (bA[oc] - mA[oc] * (gA[oc] * rsqrtf(vA[oc] + 1e-5f)))
                                  + (bB[oc] - mB[oc] * (gB[oc] * rsqrtf(vB[oc] + 1e-5f)));
                const float A0 = arow[((size_t)(b * 3 + 0) * CCH + oc) * 128 + h];
                const float A1 = arow[((size_t)(b * 3 + 1) * CCH + oc) * 128 + h];
                const float A2 = arow[((size_t)(b * 3 + 2) * CCH + oc) * 128 + h];
                const float* Bb2 = bcol + ((size_t)(b * 3 + chh) * CCH + oc) * 128;
#pragma unroll
                for (int j = 0; j < 4; ++j) {
                    const int w = warp_n * 32 + j * 8 + tq * 2;
                    float a0 = (w == 0) ? A0 : A1;
                    float a1 = (w + 1 == 127) ? A2 : A1;
                    float v0 = c[i][j][h2 * 2 + 0] + shift + a0 + Bb2[w];
                    float v1 = c[i][j][h2 * 2 + 1] + shift + a1 + Bb2[w + 1];
                    sbuf[w * 136 + ocl]       = __float2half_rn(fmaxf(v0, 0.f));
                    sbuf[(w + 1) * 136 + ocl] = __float2half_rn(fmaxf(v1, 0.f));
                }
            }
        __syncthreads();
        const int w    = tid >> 1;
        const int half = tid & 1;
        const uint4* srcp = (const uint4*)(sbuf + w * 136 + half * 64);
        uint4* gdst = (uint4*)(outh + ((size_t)b * PSZ + (size_t)(h + 1) * PH + (w + 1)) * CCH
                               + ocb + half * 64);
#pragma unroll
        for (int q = 0; q < 8; ++q) gdst[q] = srcp[q];
        return;
    }

#pragma unroll
    for (int i = 0; i < 4; ++i) {
#pragma unroll
        for (int h2 = 0; h2 < 2; ++h2) {
            const int ocl = warp_m * 64 + i * 16 + quad + h2 * 8;
            const int oc  = ocb + ocl;
            const float sh = bp[oc] - mp[oc] * (gp[oc] * rsqrtf(vp[oc] + 1e-5f));
            if (up) {
                float m = 0.f;
#pragma unroll
                for (int j = 0; j < 4; ++j) {
                    m = fmaxf(m, c[i][j][h2 * 2 + 0] + sh);
                    m = fmaxf(m, c[i][j][h2 * 2 + 1] + sh);
                }
                atomicMax((unsigned*)&rsm[ocl], __float_as_uint(fmaxf(m, 0.f)));
            } else if (EPI == 0) {
                float* cm = out1 + ((size_t)b * WWD) * CCH;
#pragma unroll
                for (int j = 0; j < 4; ++j) {
                    const int w = warp_n * 32 + j * 8 + tq * 2;
                    float v0 = fmaxf(c[i][j][h2 * 2 + 0] + sh, 0.f);
                    float v1 = fmaxf(c[i][j][h2 * 2 + 1] + sh, 0.f);
                    atomicMax((unsigned*)&cm[(size_t)w * CCH + oc],       __float_as_uint(v0));
                    atomicMax((unsigned*)&cm[(size_t)(w + 1) * CCH + oc], __float_as_uint(v1));
                }
            } else {
                size_t rowbase = ((size_t)b * CCH + oc) * HW + (size_t)h * WWD;
#pragma unroll
                for (int j = 0; j < 4; ++j) {
                    const int w = warp_n * 32 + j * 8 + tq * 2;
                    float v0 = fmaxf(c[i][j][h2 * 2 + 0] + sh, 0.f);
                    float v1 = fmaxf(c[i][j][h2 * 2 + 1] + sh, 0.f);
                    *(float2*)(out0 + rowbase + w) = make_float2(v0, v1);
                }
            }
        }
    }
    if (up) {
        __syncthreads();
        if (tid < 128)
            out0[((size_t)b * HH + h) * CCH + z * 128 + tid] = rsm[tid];
    }
}

// ---------------- rank-1 GEMM: A_k[oc,n] = sum_K Wk[oc,K]*M[n,K], K=768 ----------------
// grid: (case 3, b 4, 4: sel = z>>1 row/col, zz = z&1 oc-half)
#define GEMM_SMEM 98304
__global__ __launch_bounds__(256, 2) void rank1_gemm(
    const __half* __restrict__ wrow, const __half* __restrict__ wcol,
    const __half* __restrict__ Rmat, const __half* __restrict__ Cmat,
    float* __restrict__ Arow, float* __restrict__ Bcol)
{
    extern __shared__ char smem[];
    const uint32_t sb = cvta_smem(smem);
    const int tid = threadIdx.x;
    const int cas = blockIdx.x;
    const int b   = blockIdx.y;
    const int sel = blockIdx.z >> 1;
    const int zz  = blockIdx.z & 1;
    const __half* wb = sel ? wcol : wrow;
    const __half* M  = sel ? Cmat : Rmat;
    float* outp      = sel ? Bcol : Arow;

    const int lane = tid & 31;
    const int wid  = tid >> 5;
    const int warp_m = wid >> 2;
    const int warp_n = wid & 3;
    const int lrow = lane & 15;
    const int lcol = lane >> 4;

    float c[4][4][4];
#pragma unroll
    for (int i = 0; i < 4; ++i)
#pragma unroll
        for (int j = 0; j < 4; ++j)
#pragma unroll
            for (int r = 0; r < 4; ++r) c[i][j][r] = 0.f;

    auto stage_w = [&](int s) {
        const uint32_t base = sb + (uint32_t)(s % 3) * 16384;
        const char* asrc = (const char*)wb + (size_t)((cas * 2 + zz) * 12 + s) * 16384;
#pragma unroll
        for (int t = 0; t < 4; ++t) {
            int i = tid + t * 256;
            cpa16(base + i * 16, asrc + i * 16);
        }
    };
    auto stage_b = [&](int s) {
        const uint32_t base = sb + 49152 + (uint32_t)(s % 3) * 16384;
        const __half* bp = M + (size_t)b * 128 * 768 + s * 64;
        for (int i = tid; i < 1024; i += 256) {
            int n  = i >> 3;
            int kc = i & 7;
            cpa16(base + n * 128 + ((kc ^ (n & 7)) * 16), bp + (size_t)n * 768 + kc * 8);
        }
    };

    stage_w(0); stage_b(0); CP_COMMIT();
    for (int s = 0; s < 12; ++s) {
        if (s + 1 < 12) { stage_w(s + 1); stage_b(s + 1); CP_COMMIT(); CP_WAIT(1); }
        else            { CP_WAIT(0); }
        __syncthreads();
        const uint32_t Ab = sb + (uint32_t)(s % 3) * 16384;
        const uint32_t Bb = sb + 49152 + (uint32_t)(s % 3) * 16384;
#pragma unroll
        for (int kk = 0; kk < 4; ++kk) {
            const int kc = kk * 2 + lcol;
            uint32_t a[4][4], bbf[4][2];
#pragma unroll
            for (int i = 0; i < 4; ++i) {
                int row = warp_m * 64 + i * 16 + lrow;
                ldsm4(a[i], Ab + (uint32_t)(row * 128 + ((kc ^ (row & 7)) * 16)));
            }
#pragma unroll
            for (int j = 0; j < 2; ++j) {
                int row = warp_n * 32 + j * 16 + lrow;
                uint32_t q[4];
                ldsm4(q, Bb + (uint32_t)(row * 128 + ((kc ^ (row & 7)) * 16)));
                bbf[j * 2 + 0][0] = q[0]; bbf[j * 2 + 0][1] = q[2];
                bbf[j * 2 + 1][0] = q[1]; bbf[j * 2 + 1][1] = q[3];
            }
#pragma unroll
            for (int i = 0; i < 4; ++i)
#pragma unroll
                for (int j = 0; j < 4; ++j) mma16816(c[i][j], a[i], bbf[j]);
        }
        __syncthreads();
    }

    const int quad = lane >> 2;
    const int tq   = lane & 3;
#pragma unroll
    for (int i = 0; i < 4; ++i)
#pragma unroll
        for (int h2 = 0; h2 < 2; ++h2) {
            const int oc = zz * 128 + warp_m * 64 + i * 16 + quad + h2 * 8;
            size_t rowbase = ((size_t)(b * 3 + cas) * CCH + oc) * 128;
#pragma unroll
            for (int j = 0; j < 4; ++j) {
                const int n = warp_n * 32 + j * 8 + tq * 2;
                *(float2*)(outp + rowbase + n) =
                    make_float2(c[i][j][h2 * 2 + 0], c[i][j][h2 * 2 + 1]);
            }
        }
}

// ---------------- weight prepack (full conv blobs) ----------------
__global__ void prepack_kernel(const float* __restrict__ srcA, const float* __restrict__ srcB,
                               const float* __restrict__ gSA, const float* __restrict__ vSA,
                               const float* __restrict__ gSB, const float* __restrict__ vSB,
                               int zsplit, int NSH, __half* __restrict__ blob, int total)
{
    int idx = blockIdx.x * 256 + threadIdx.x;
    if (idx >= total) return;
    int icl  = idx & 63;
    int ocl  = (idx >> 6) & 127;
    int rest = idx >> 13;
    int r = rest % NSH; rest /= NSH;
    int chunk = rest & 3;
    int zz    = rest >> 2;
    const float* src = srcA;
    const float* gS = gSA;
    const float* vS = vSA;
    int o = zz * 128 + ocl;
    if (zz >= zsplit) { src = srcB; gS = gSB; vS = vSB; o = (zz - zsplit) * 128 + ocl; }
    int ic = chunk * 64 + icl;
    float sc = gS[o] * rsqrtf(vS[o] + 1e-5f);
    float w = src[(size_t)(o * 256 + ic) * NSH + r] * sc;
    size_t base = (size_t)((zz * 4 + chunk) * NSH + r) * 8192;
    uint32_t off = (uint32_t)(ocl * 64 + (((icl >> 3) ^ (ocl & 7)) * 8) + (icl & 7));
    blob[base + off] = __float2half_rn(w);
}

// ---------------- rank-1 weight prepack: 3-case dx/dy-summed conv_p weights ----------------
__global__ void prepack_rank1(const float* __restrict__ wp,
                              const float* __restrict__ gS, const float* __restrict__ vS,
                              int rowmode, __half* __restrict__ blob)
{
    int idx = blockIdx.x * 256 + threadIdx.x;
    if (idx >= 3 * 2 * 12 * 8192) return;
    int icl  = idx & 63;
    int ocl  = (idx >> 6) & 127;
    int rest = idx >> 13;
    int chunk = rest % 12; rest /= 12;
    int zz  = rest & 1;
    int cas = rest >> 1;
    int k  = chunk * 64 + icl;
    int d  = k >> 8;       // dy (rowmode) or dx (colmode)
    int ic = k & 255;
    int o  = zz * 128 + ocl;
    float sc = gS[o] * rsqrtf(vS[o] + 1e-5f);
    int lo = (cas == 0) ? 1 : 0, hi = (cas == 2) ? 1 : 2;
    float v = 0.f;
    for (int t = lo; t <= hi; ++t)
        v += rowmode ? wp[((size_t)(o * 256 + ic) * 3 + d) * 3 + t]
                     : wp[((size_t)(o * 256 + ic) * 3 + t) * 3 + d];
    v *= sc;
    size_t base = (size_t)((cas * 2 + zz) * 12 + chunk) * 8192;
    uint32_t off = (uint32_t)(ocl * 64 + (((icl >> 3) ^ (ocl & 7)) * 8) + (icl & 7));
    blob[base + off] = __float2half_rn(v);
}

// ---------------- R/C matrix build from row/col maxes ----------------
__global__ void rc_build(const float* __restrict__ rmaxT, const float* __restrict__ cmaxT,
                         __half* __restrict__ R, __half* __restrict__ C)
{
    int idx = blockIdx.x * 256 + threadIdx.x;   // 2*4*128*768
    const int N1 = BBATCH * 128 * 768;
    int sel = idx >= N1;
    int i = sel ? idx - N1 : idx;
    int k = i % 768;
    int n = (i / 768) & 127;
    int b = i / (768 * 128);
    int d = k >> 8, ic = k & 255;
    int y = n + d - 1;
    const float* src = sel ? cmaxT : rmaxT;
    float v = (y >= 0 && y < 128) ? src[((size_t)b * 128 + y) * CCH + ic] : 0.f;
    (sel ? C : R)[((size_t)b * 128 + n) * 768 + k] = __float2half_rn(v);
}

// ---------------- zero borders + cmax accumulator ----------------
__global__ void zero_border_kernel(__half* a, __half* b, float* cmax) {
    int idx = blockIdx.x * 256 + threadIdx.x;
    const int NB = 4 * 516 * 256;
    if (idx < NB) {
        int ch   = idx & 255;
        int rest = idx >> 8;
        int p    = rest % 516;
        int bb   = rest / 516;
        int h, w;
        if (p < 260) { h = (p < 130) ? 0 : 129; w = p % 130; }
        else         { int q = p - 260; h = 1 + (q & 127); w = (q >> 7) * 129; }
        size_t i = ((size_t)bb * PSZ + (size_t)h * PH + w) * CCH + ch;
        a[i] = __float2half(0.f); b[i] = __float2half(0.f);
    } else {
        int j = idx - NB;
        if (j < BBATCH * WWD * CCH) cmax[j] = 0.f;
    }
}

// ---------------- fp32 NCHW -> padded [h][w][c] fp16 ----------------
__global__ void pad_convert_kernel(const float* __restrict__ src, __half* __restrict__ dst)
{
    __shared__ float s[256][33];
    const int w0 = blockIdx.x * 32;
    const int h  = blockIdx.y;
    const int b  = blockIdx.z;
    const int tid = threadIdx.x;
    const int wl8 = tid & 31;
#pragma unroll 4
    for (int i = 0; i < 32; ++i) {
        int c = i * 8 + (tid >> 5);
        s[c][wl8] = src[((size_t)(b * CCH + c) * HH + h) * WWD + w0 + wl8];
    }
    __syncthreads();
    const int wl = tid >> 3;
    const int cg = (tid & 7) * 32;
    __align__(16) __half v16[32];
#pragma unroll
    for (int j = 0; j < 32; ++j)
        v16[j] = __float2half_rn(s[cg + j][wl]);
    size_t base = ((size_t)b * PSZ + (size_t)(h + 1) * PH + (w0 + wl + 1)) * CCH + cg;
    uint4* dp = (uint4*)(dst + base);
    const uint4* vs = (const uint4*)v16;
#pragma unroll
    for (int q = 0; q < 4; ++q) dp[q] = vs[q];
}

// ---------------- launch ----------------
extern "C" void kernel_launch(void* const* d_in, const int* in_sizes, int n_in,
                              void* d_out, int out_size) {
    (void)in_sizes; (void)n_in; (void)out_size;
    const float* x      = (const float*)d_in[0];
    const float* w_up   = (const float*)d_in[1];
    const float* g_up   = (const float*)d_in[2];
    const float* b_up   = (const float*)d_in[3];
    const float* m_up   = (const float*)d_in[4];
    const float* v_up   = (const float*)d_in[5];
    const float* w_down = (const float*)d_in[6];
    const float* g_down = (const float*)d_in[7];
    const float* b_down = (const float*)d_in[8];
    const float* m_down = (const float*)d_in[9];
    const float* v_down = (const float*)d_in[10];
    const float* w_p    = (const float*)d_in[11];
    const float* g_p    = (const float*)d_in[12];
    const float* b_p    = (const float*)d_in[13];
    const float* m_p    = (const float*)d_in[14];
    const float* v_p    = (const float*)d_in[15];
    const float* w_c1   = (const float*)d_in[16];
    const float* g_c1   = (const float*)d_in[17];
    const float* b_c1   = (const float*)d_in[18];
    const float* m_c1   = (const float*)d_in[19];
    const float* v_c1   = (const float*)d_in[20];
    const float* w_c2   = (const float*)d_in[21];
    const float* g_c2   = (const float*)d_in[22];
    const float* b_c2   = (const float*)d_in[23];
    const float* m_c2   = (const float*)d_in[24];
    const float* v_c2   = (const float*)d_in[25];
    float* out = (float*)d_out;

    float *rmaxT, *cmaxT, *Arow, *Bcol;
    __half *px, *pt2, *bl1, *blC2, *blC1, *blR, *blC, *Rm, *Cm;
    cudaGetSymbolAddress((void**)&rmaxT, g_rmaxT);
    cudaGetSymbolAddress((void**)&cmaxT, g_cmaxT);
    cudaGetSymbolAddress((void**)&Arow,  g_Arow);
    cudaGetSymbolAddress((void**)&Bcol,  g_Bcol);
    cudaGetSymbolAddress((void**)&px,    g_px);
    cudaGetSymbolAddress((void**)&pt2,   g_pt2);
    cudaGetSymbolAddress((void**)&bl1,   g_blob1);
    cudaGetSymbolAddress((void**)&blC2,  g_blobC2);
    cudaGetSymbolAddress((void**)&blC1,  g_blobC1);
    cudaGetSymbolAddress((void**)&blR,   g_blR);
    cudaGetSymbolAddress((void**)&blC,   g_blC);
    cudaGetSymbolAddress((void**)&Rm,    g_R);
    cudaGetSymbolAddress((void**)&Cm,    g_C);

    cudaFuncSetAttribute(conv_mma<0>, cudaFuncAttributeMaxDynamicSharedMemorySize, CONV_SMEM);
    cudaFuncSetAttribute(conv_mma<1>, cudaFuncAttributeMaxDynamicSharedMemorySize, CONV_SMEM);
    cudaFuncSetAttribute(conv_mma<2>, cudaFuncAttributeMaxDynamicSharedMemorySize, CONV_SMEM);
    cudaFuncSetAttribute(rank1_gemm,  cudaFuncAttributeMaxDynamicSharedMemorySize, GEMM_SMEM);

    prepack_kernel<<<1179648/256, 256>>>(w_up, w_down, g_up, v_up, g_down, v_down, 2, 9, bl1, 1179648);
    prepack_kernel<<<589824/256,  256>>>(w_c2, w_c2, g_c2, v_c2, g_c2, v_c2, 2, 9, blC2, 589824);
    prepack_kernel<<<65536/256,   256>>>(w_c1, w_c1, g_c1, v_c1, g_c1, v_c1, 2, 1, blC1, 65536);
    prepack_rank1<<<589824/256, 256>>>(w_p, g_p, v_p, 1, blR);
    prepack_rank1<<<589824/256, 256>>>(w_p, g_p, v_p, 0, blC);
    zero_border_kernel<<<(4*516*256 + 4*128*256)/256, 256>>>(px, pt2, cmaxT);
    pad_convert_kernel<<<dim3(4,128,4), 256>>>(x, px);

    // fused up+down: z0,1 -> rmaxT; z2,3 -> atomic colmax into cmaxT
    conv_mma<0><<<dim3(HH,BBATCH,4), 256, CONV_SMEM>>>(px, bl1,
        g_up, b_up, m_up, v_up, g_down, b_down, m_down, v_down,
        rmaxT, cmaxT, nullptr, nullptr, nullptr);

    // build R/C matrices, then rank-1 conv_p GEMMs
    rc_build<<<(2*BBATCH*128*768)/256, 256>>>(rmaxT, cmaxT, Rm, Cm);
    rank1_gemm<<<dim3(3,BBATCH,4), 256, GEMM_SMEM>>>(blR, blC, Rm, Cm, Arow, Bcol);

    // relu1 = relu(conv_c1(x) + A + B + shifts) -> pt2 (fp16 padded)
    conv_mma<1><<<dim3(HH,BBATCH,2), 256, CONV_SMEM>>>(px, blC1,
        g_p, b_p, m_p, v_p, g_c1, b_c1, m_c1, v_c1,
        nullptr, nullptr, pt2, Arow, Bcol);

    // out = relu(conv_c2(relu1) + sh_c2)
    conv_mma<2><<<dim3(HH,BBATCH,2), 256, CONV_SMEM>>>(pt2, blC2,
        g_c2, b_c2, m_c2, v_c2, g_c2, b_c2, m_c2, v_c2,
        out, nullptr, nullptr, nullptr, nullptr);
}